// round 1
// baseline (speedup 1.0000x reference)
#include <cuda_runtime.h>
#include <math.h>

#define DIM    256
#define INNER  512
#define HEADS  8
#define DHEAD  64
#define NTOK   49
#define NPIX   3136
#define BATCH  16
#define NWIN   64
#define EPS    1e-5f

// Scratch (allocation-free: __device__ globals)
__device__ float g_y[3][BATCH * DIM * NPIX];      // dwconv+BN outputs (q,k,v): [b][c][pix]
__device__ float g_qkv[3][BATCH * INNER * NPIX];  // projected, windowed: [b][h][w][d][t]
__device__ float g_att[BATCH * INNER * NPIX];     // attention out, plain: [b][ci][y][x]
__device__ float g_bias[HEADS * NTOK * NTOK];     // rel-pos bias: [h][i][j]

// ---------------------------------------------------------------------------
// Kernel C: precompute relative position bias table [h][i][j]
// ---------------------------------------------------------------------------
__global__ void bias_kernel(const float* __restrict__ pos) {
    int idx = blockIdx.x * 256 + threadIdx.x;
    if (idx >= HEADS * NTOK * NTOK) return;
    int h = idx / (NTOK * NTOK);
    int r = idx % (NTOK * NTOK);
    int i = r / NTOK, j = r % NTOK;
    int xi = i / 7, yi = i % 7, xj = j / 7, yj = j % 7;
    int rel = (xj - xi + 6) * 13 + (yj - yi + 6);
    g_bias[idx] = __ldg(pos + rel * HEADS + h);
}

// ---------------------------------------------------------------------------
// Kernel A: depthwise 3x3 conv + BN (eval) for all 3 projections, x read once
// ---------------------------------------------------------------------------
__global__ void __launch_bounds__(256) dwbn_kernel(
    const float* __restrict__ x,
    const float* __restrict__ dwq, const float* __restrict__ gq, const float* __restrict__ bq,
    const float* __restrict__ mq,  const float* __restrict__ vq,
    const float* __restrict__ dwk, const float* __restrict__ gk, const float* __restrict__ bk,
    const float* __restrict__ mk,  const float* __restrict__ vk,
    const float* __restrict__ dwv, const float* __restrict__ gv, const float* __restrict__ bv,
    const float* __restrict__ mv,  const float* __restrict__ vv)
{
    int p = blockIdx.x * 256 + threadIdx.x;
    if (p >= NPIX) return;
    int bc = blockIdx.y;            // b*256 + c
    int c  = bc & (DIM - 1);
    const float* xp = x + (size_t)bc * NPIX;
    int y0 = p / 56, x0 = p % 56;

    float t[9];
#pragma unroll
    for (int dy = 0; dy < 3; dy++)
#pragma unroll
        for (int dx = 0; dx < 3; dx++) {
            int yy = y0 + dy - 1, xx = x0 + dx - 1;
            t[dy * 3 + dx] = (yy >= 0 && yy < 56 && xx >= 0 && xx < 56)
                           ? __ldg(xp + yy * 56 + xx) : 0.f;
        }

    const float* DW[3] = {dwq, dwk, dwv};
    const float* GG[3] = {gq, gk, gv};
    const float* BB[3] = {bq, bk, bv};
    const float* MM[3] = {mq, mk, mv};
    const float* VV[3] = {vq, vk, vv};

#pragma unroll
    for (int pr = 0; pr < 3; pr++) {
        float acc = 0.f;
        const float* wp = DW[pr] + c * 9;
#pragma unroll
        for (int j = 0; j < 9; j++) acc += t[j] * __ldg(wp + j);
        float sc = __ldg(GG[pr] + c) * rsqrtf(__ldg(VV[pr] + c) + EPS);
        float sh = __ldg(BB[pr] + c) - __ldg(MM[pr] + c) * sc;
        g_y[pr][(size_t)bc * NPIX + p] = acc * sc + sh;
    }
}

// ---------------------------------------------------------------------------
// Kernel B: 1x1 pointwise proj GEMM  out[inner, pix] = pw[inner, c] * y[c, pix]
// Tiles: BM=128 (inner), BN=64 (pix), BK=16; 256 threads; micro 8x4.
// Writes q/k/v directly in windowed layout [b][h][w][d][t].
// ---------------------------------------------------------------------------
__global__ void __launch_bounds__(256) proj_gemm(
    const float* __restrict__ pw0, const float* __restrict__ pw1,
    const float* __restrict__ pw2)
{
    int nb = blockIdx.x;                 // 0..48
    int mb = blockIdx.y;                 // 0..3
    int bz = blockIdx.z;                 // b*3 + proj
    int pr = bz % 3, b = bz / 3;
    const float* A = (pr == 0) ? pw0 : ((pr == 1) ? pw1 : pw2);
    const float* B = g_y[pr] + (size_t)b * DIM * NPIX;

    __shared__ float As[16][128];
    __shared__ float Bs[16][64];

    int tid = threadIdx.x;
    int tx = tid & 15, ty = tid >> 4;
    int m0 = mb * 128, n0 = nb * 64;

    float acc[8][4];
#pragma unroll
    for (int i = 0; i < 8; i++)
#pragma unroll
        for (int j = 0; j < 4; j++) acc[i][j] = 0.f;

    for (int k0 = 0; k0 < DIM; k0 += 16) {
#pragma unroll
        for (int i = 0; i < 2; i++) {
            int idx = tid * 2 + i;
            int row = idx >> 2, kq = (idx & 3) * 4;
            float4 va = *(const float4*)(A + (size_t)(m0 + row) * DIM + k0 + kq);
            As[kq + 0][row] = va.x; As[kq + 1][row] = va.y;
            As[kq + 2][row] = va.z; As[kq + 3][row] = va.w;
        }
        {
            int row = tid >> 4, cq = (tid & 15) * 4;
            *(float4*)&Bs[row][cq] =
                *(const float4*)(B + (size_t)(k0 + row) * NPIX + n0 + cq);
        }
        __syncthreads();
#pragma unroll
        for (int k = 0; k < 16; k++) {
            float a[8], bb[4];
            *(float4*)&a[0] = *(float4*)&As[k][ty * 8];
            *(float4*)&a[4] = *(float4*)&As[k][ty * 8 + 4];
            *(float4*)&bb[0] = *(float4*)&Bs[k][tx * 4];
#pragma unroll
            for (int mm = 0; mm < 8; mm++)
#pragma unroll
                for (int nn = 0; nn < 4; nn++)
                    acc[mm][nn] += a[mm] * bb[nn];
        }
        __syncthreads();
    }

    float* Out = g_qkv[pr] + (size_t)b * INNER * NPIX;
#pragma unroll
    for (int mm = 0; mm < 8; mm++) {
        int m = m0 + ty * 8 + mm;
        int h = m >> 6, d = m & 63;
#pragma unroll
        for (int nn = 0; nn < 4; nn++) {
            int n = n0 + tx * 4 + nn;
            int yy = n / 56, xx = n % 56;
            int w = (yy / 7) * 8 + (xx / 7);
            int t = (yy % 7) * 7 + (xx % 7);
            Out[((size_t)(h * NWIN + w) * DHEAD + d) * NTOK + t] = acc[mm][nn];
        }
    }
}

// ---------------------------------------------------------------------------
// Kernel D: windowed attention. One CTA per (b, h, w): 49 tokens, d=64.
// dots = Q K^T * 0.125 + bias -> softmax -> out = attn V (computed transposed)
// Static smem 49,096 B (attnT aliases the dead q tile).
// ---------------------------------------------------------------------------
__global__ void __launch_bounds__(256) attn_kernel() {
    __shared__ float qs[64 * 52 + 16];  // [kk][t] stride 52; later aliased as attnT [j][i] stride 68
    __shared__ float ks[64 * 52 + 16];  // [kk][t] stride 52
    __shared__ float vs[64 * 49];       // [d][t]
    __shared__ float dots[49 * 50];     // [i][j] stride 50

    int w = blockIdx.x, h = blockIdx.y, b = blockIdx.z;
    int tid = threadIdx.x;
    size_t base = ((size_t)(b * HEADS + h) * NWIN + w) * (DHEAD * NTOK);
    const float* qg = g_qkv[0] + base;
    const float* kg = g_qkv[1] + base;
    const float* vg = g_qkv[2] + base;

    for (int idx = tid; idx < DHEAD * NTOK; idx += 256) {
        int dd = idx / NTOK, t = idx - dd * NTOK;
        qs[dd * 52 + t] = qg[idx];
        ks[dd * 52 + t] = kg[idx];
        vs[idx] = vg[idx];
    }
    __syncthreads();

    int tx = tid & 15, ty = tid >> 4;

    // ---- dots: i = ty*4+mm, j = tx*4+nn (padded to 64x64, only <49 stored)
    float acc[4][4];
#pragma unroll
    for (int i = 0; i < 4; i++)
#pragma unroll
        for (int j = 0; j < 4; j++) acc[i][j] = 0.f;

#pragma unroll 8
    for (int kk = 0; kk < 64; kk++) {
        float a[4], bb[4];
        *(float4*)a  = *(const float4*)&qs[kk * 52 + ty * 4];
        *(float4*)bb = *(const float4*)&ks[kk * 52 + tx * 4];
#pragma unroll
        for (int mm = 0; mm < 4; mm++)
#pragma unroll
            for (int nn = 0; nn < 4; nn++)
                acc[mm][nn] += a[mm] * bb[nn];
    }

    const float* bptr = g_bias + h * NTOK * NTOK;
#pragma unroll
    for (int mm = 0; mm < 4; mm++) {
        int i = ty * 4 + mm;
        if (i < NTOK) {
#pragma unroll
            for (int nn = 0; nn < 4; nn++) {
                int j = tx * 4 + nn;
                if (j < NTOK)
                    dots[i * 50 + j] = acc[mm][nn] * 0.125f + __ldg(bptr + i * NTOK + j);
            }
        }
    }
    __syncthreads();

    // ---- softmax (warp per row), writing transposed attnT[j][i] (stride 68)
    float* attnT = qs;  // q tile dead from here on
    int warp = tid >> 5, lane = tid & 31;
    for (int i = warp; i < NTOK; i += 8) {
        float v1 = dots[i * 50 + lane];
        float v2 = (lane + 32 < NTOK) ? dots[i * 50 + lane + 32] : -1e30f;
        float mx = fmaxf(v1, v2);
#pragma unroll
        for (int o = 16; o > 0; o >>= 1) mx = fmaxf(mx, __shfl_xor_sync(0xffffffffu, mx, o));
        float e1 = __expf(v1 - mx);
        float e2 = (lane + 32 < NTOK) ? __expf(v2 - mx) : 0.f;
        float s = e1 + e2;
#pragma unroll
        for (int o = 16; o > 0; o >>= 1) s += __shfl_xor_sync(0xffffffffu, s, o);
        float inv = 1.f / s;
        attnT[lane * 68 + i] = e1 * inv;
        if (lane + 32 < NTOK) attnT[(lane + 32) * 68 + i] = e2 * inv;
    }
    __syncthreads();

    // ---- AV transposed: outT[d][i] = sum_j vs[d][j] * attnT[j][i]
    float o[4][4];
#pragma unroll
    for (int i = 0; i < 4; i++)
#pragma unroll
        for (int j = 0; j < 4; j++) o[i][j] = 0.f;

#pragma unroll 7
    for (int j = 0; j < NTOK; j++) {
        float a[4], bb[4];
#pragma unroll
        for (int mm = 0; mm < 4; mm++) a[mm] = vs[(ty * 4 + mm) * NTOK + j];
        *(float4*)bb = *(const float4*)&attnT[j * 68 + tx * 4];
#pragma unroll
        for (int mm = 0; mm < 4; mm++)
#pragma unroll
            for (int nn = 0; nn < 4; nn++)
                o[mm][nn] += a[mm] * bb[nn];
    }

    // ---- un-window at write: plain [b][ci][y][x]
    int nh = w >> 3, nw2 = w & 7;
    float* outp = g_att + (size_t)b * INNER * NPIX + (size_t)h * DHEAD * NPIX;
#pragma unroll
    for (int nn = 0; nn < 4; nn++) {
        int i = tx * 4 + nn;
        if (i < NTOK) {
            int yy = nh * 7 + i / 7;
            int xx = nw2 * 7 + i % 7;
            int poff = yy * 56 + xx;
#pragma unroll
            for (int mm = 0; mm < 4; mm++) {
                int d = ty * 4 + mm;
                outp[(size_t)d * NPIX + poff] = o[mm][nn];
            }
        }
    }
}

// ---------------------------------------------------------------------------
// Kernel E: final 1x1 conv GEMM  out[co, pix] = out_w[co, ci] * att[ci, pix] + b
// Same tiling as proj_gemm, K=512, plain coalesced in/out.
// ---------------------------------------------------------------------------
__global__ void __launch_bounds__(256) out_gemm(
    const float* __restrict__ A, const float* __restrict__ ob,
    float* __restrict__ out)
{
    int nb = blockIdx.x;                 // 0..48
    int mb = blockIdx.y;                 // 0..1
    int b  = blockIdx.z;                 // 0..15
    const float* B = g_att + (size_t)b * INNER * NPIX;

    __shared__ float As[16][128];
    __shared__ float Bs[16][64];

    int tid = threadIdx.x;
    int tx = tid & 15, ty = tid >> 4;
    int m0 = mb * 128, n0 = nb * 64;

    float acc[8][4];
#pragma unroll
    for (int i = 0; i < 8; i++)
#pragma unroll
        for (int j = 0; j < 4; j++) acc[i][j] = 0.f;

    for (int k0 = 0; k0 < INNER; k0 += 16) {
#pragma unroll
        for (int i = 0; i < 2; i++) {
            int idx = tid * 2 + i;
            int row = idx >> 2, kq = (idx & 3) * 4;
            float4 va = *(const float4*)(A + (size_t)(m0 + row) * INNER + k0 + kq);
            As[kq + 0][row] = va.x; As[kq + 1][row] = va.y;
            As[kq + 2][row] = va.z; As[kq + 3][row] = va.w;
        }
        {
            int row = tid >> 4, cq = (tid & 15) * 4;
            *(float4*)&Bs[row][cq] =
                *(const float4*)(B + (size_t)(k0 + row) * NPIX + n0 + cq);
        }
        __syncthreads();
#pragma unroll
        for (int k = 0; k < 16; k++) {
            float a[8], bb[4];
            *(float4*)&a[0] = *(float4*)&As[k][ty * 8];
            *(float4*)&a[4] = *(float4*)&As[k][ty * 8 + 4];
            *(float4*)&bb[0] = *(float4*)&Bs[k][tx * 4];
#pragma unroll
            for (int mm = 0; mm < 8; mm++)
#pragma unroll
                for (int nn = 0; nn < 4; nn++)
                    acc[mm][nn] += a[mm] * bb[nn];
        }
        __syncthreads();
    }

#pragma unroll
    for (int mm = 0; mm < 8; mm++) {
        int m = m0 + ty * 8 + mm;
        float bias = __ldg(ob + m);
#pragma unroll
        for (int nn = 0; nn < 4; nn++) {
            int n = n0 + tx * 4 + nn;
            out[(size_t)(b * DIM + m) * NPIX + n] = acc[mm][nn] + bias;
        }
    }
}

// ---------------------------------------------------------------------------
extern "C" void kernel_launch(void* const* d_in, const int* in_sizes, int n_in,
                              void* d_out, int out_size) {
    const float* x   = (const float*)d_in[0];
    const float* qdw = (const float*)d_in[1];
    const float* qg  = (const float*)d_in[2];
    const float* qb  = (const float*)d_in[3];
    const float* qm  = (const float*)d_in[4];
    const float* qv  = (const float*)d_in[5];
    const float* qpw = (const float*)d_in[6];
    const float* kdw = (const float*)d_in[7];
    const float* kg  = (const float*)d_in[8];
    const float* kb  = (const float*)d_in[9];
    const float* km  = (const float*)d_in[10];
    const float* kv  = (const float*)d_in[11];
    const float* kpw = (const float*)d_in[12];
    const float* vdw = (const float*)d_in[13];
    const float* vg  = (const float*)d_in[14];
    const float* vb  = (const float*)d_in[15];
    const float* vm  = (const float*)d_in[16];
    const float* vv  = (const float*)d_in[17];
    const float* vpw = (const float*)d_in[18];
    const float* pos = (const float*)d_in[19];
    const float* ow  = (const float*)d_in[20];
    const float* obias = (const float*)d_in[21];
    float* out = (float*)d_out;

    bias_kernel<<<(HEADS * NTOK * NTOK + 255) / 256, 256>>>(pos);

    dwbn_kernel<<<dim3((NPIX + 255) / 256, BATCH * DIM), 256>>>(
        x, qdw, qg, qb, qm, qv, kdw, kg, kb, km, kv, vdw, vg, vb, vm, vv);

    proj_gemm<<<dim3(49, 4, BATCH * 3), 256>>>(qpw, kpw, vpw);

    attn_kernel<<<dim3(NWIN, HEADS, BATCH), 256>>>();

    out_gemm<<<dim3(49, 2, BATCH), 256>>>(ow, obias, out);
}

// round 2
// speedup vs baseline: 1.1088x; 1.1088x over previous
#include <cuda_runtime.h>
#include <math.h>
#include <stdint.h>

#define DIM    256
#define INNER  512
#define HEADS  8
#define DHEAD  64
#define NTOK   49
#define NPIX   3136
#define BATCH  16
#define NWIN   64
#define EPS    1e-5f

// Scratch (allocation-free: __device__ globals)
__device__ float g_y[3][BATCH * DIM * NPIX];      // dwconv+BN outputs (q,k,v): [b][c][pix]
__device__ float g_qkv[3][BATCH * INNER * NPIX];  // projected, windowed: [b][h][w][d][t]
__device__ float g_att[BATCH * INNER * NPIX];     // attention out, plain: [b][ci][y][x]
__device__ float g_bias[HEADS * NTOK * NTOK];     // rel-pos bias: [h][i][j]

// ---------------------------------------------------------------------------
// tf32 helpers
// ---------------------------------------------------------------------------
__device__ __forceinline__ uint32_t f2tf(float f) {
    uint32_t u;
    asm("cvt.rna.tf32.f32 %0, %1;" : "=r"(u) : "f"(f));
    return u;
}

__device__ __forceinline__ void mma_tf32(float c[4], const uint32_t a[4], const uint32_t b[2]) {
    asm volatile(
        "mma.sync.aligned.m16n8k8.row.col.f32.tf32.tf32.f32 "
        "{%0,%1,%2,%3}, {%4,%5,%6,%7}, {%8,%9}, {%0,%1,%2,%3};\n"
        : "+f"(c[0]), "+f"(c[1]), "+f"(c[2]), "+f"(c[3])
        : "r"(a[0]), "r"(a[1]), "r"(a[2]), "r"(a[3]), "r"(b[0]), "r"(b[1]));
}

// ---------------------------------------------------------------------------
// Kernel C: precompute relative position bias table [h][i][j]
// ---------------------------------------------------------------------------
__global__ void bias_kernel(const float* __restrict__ pos) {
    int idx = blockIdx.x * 256 + threadIdx.x;
    if (idx >= HEADS * NTOK * NTOK) return;
    int h = idx / (NTOK * NTOK);
    int r = idx % (NTOK * NTOK);
    int i = r / NTOK, j = r % NTOK;
    int xi = i / 7, yi = i % 7, xj = j / 7, yj = j % 7;
    int rel = (xj - xi + 6) * 13 + (yj - yi + 6);
    g_bias[idx] = __ldg(pos + rel * HEADS + h);
}

// ---------------------------------------------------------------------------
// Kernel A: depthwise 3x3 conv + BN (eval) for all 3 projections, x read once
// ---------------------------------------------------------------------------
__global__ void __launch_bounds__(256) dwbn_kernel(
    const float* __restrict__ x,
    const float* __restrict__ dwq, const float* __restrict__ gq, const float* __restrict__ bq,
    const float* __restrict__ mq,  const float* __restrict__ vq,
    const float* __restrict__ dwk, const float* __restrict__ gk, const float* __restrict__ bk,
    const float* __restrict__ mk,  const float* __restrict__ vk,
    const float* __restrict__ dwv, const float* __restrict__ gv, const float* __restrict__ bv,
    const float* __restrict__ mv,  const float* __restrict__ vv)
{
    int p = blockIdx.x * 256 + threadIdx.x;
    if (p >= NPIX) return;
    int bc = blockIdx.y;            // b*256 + c
    int c  = bc & (DIM - 1);
    const float* xp = x + (size_t)bc * NPIX;
    int y0 = p / 56, x0 = p % 56;

    float t[9];
#pragma unroll
    for (int dy = 0; dy < 3; dy++)
#pragma unroll
        for (int dx = 0; dx < 3; dx++) {
            int yy = y0 + dy - 1, xx = x0 + dx - 1;
            t[dy * 3 + dx] = (yy >= 0 && yy < 56 && xx >= 0 && xx < 56)
                           ? __ldg(xp + yy * 56 + xx) : 0.f;
        }

    const float* DW[3] = {dwq, dwk, dwv};
    const float* GG[3] = {gq, gk, gv};
    const float* BB[3] = {bq, bk, bv};
    const float* MM[3] = {mq, mk, mv};
    const float* VV[3] = {vq, vk, vv};

#pragma unroll
    for (int pr = 0; pr < 3; pr++) {
        float acc = 0.f;
        const float* wp = DW[pr] + c * 9;
#pragma unroll
        for (int j = 0; j < 9; j++) acc += t[j] * __ldg(wp + j);
        float sc = __ldg(GG[pr] + c) * rsqrtf(__ldg(VV[pr] + c) + EPS);
        float sh = __ldg(BB[pr] + c) - __ldg(MM[pr] + c) * sc;
        g_y[pr][(size_t)bc * NPIX + p] = acc * sc + sh;
    }
}

// ---------------------------------------------------------------------------
// Kernel B (tf32 tensor core): proj GEMM out[inner, pix] = pw[inner,c]*y[c,pix]
// BM=128, BN=128, BK=16; 8 warps (2x4), warp tile 64x32; mma.m16n8k8 tf32.
// Writes q/k/v directly in windowed layout [b][h][w][d][t].
// ---------------------------------------------------------------------------
__global__ void __launch_bounds__(256, 2) proj_gemm_tc(
    const float* __restrict__ pw0, const float* __restrict__ pw1,
    const float* __restrict__ pw2)
{
    __shared__ uint32_t As[128 * 20];   // [m][k] stride 20 (conflict-free quads)
    __shared__ uint32_t Bs[16 * 136];   // [k][n] stride 136 (conflict-free quads)

    int nb = blockIdx.x;                 // 0..24
    int mb = blockIdx.y;                 // 0..3
    int bz = blockIdx.z;                 // b*3 + proj
    int pr = bz % 3, b = bz / 3;
    const float* A = (pr == 0) ? pw0 : ((pr == 1) ? pw1 : pw2);
    const float* B = g_y[pr] + (size_t)b * DIM * NPIX;

    int tid = threadIdx.x;
    int lane = tid & 31, warp = tid >> 5;
    int wm = (warp & 1) * 64;
    int wn = (warp >> 1) * 32;
    int m0 = mb * 128, n0 = nb * 128;

    float acc[4][4][4];
#pragma unroll
    for (int mt = 0; mt < 4; mt++)
#pragma unroll
        for (int nt = 0; nt < 4; nt++)
#pragma unroll
            for (int i = 0; i < 4; i++) acc[mt][nt][i] = 0.f;

    for (int k0 = 0; k0 < DIM; k0 += 16) {
        // stage A tile: 128x16, convert to tf32
#pragma unroll
        for (int i = 0; i < 2; i++) {
            int idx = tid * 2 + i;
            int row = idx >> 2, k4 = (idx & 3) * 4;
            float4 v = *(const float4*)(A + (size_t)(m0 + row) * DIM + k0 + k4);
            uint32_t* d = &As[row * 20 + k4];
            d[0] = f2tf(v.x); d[1] = f2tf(v.y); d[2] = f2tf(v.z); d[3] = f2tf(v.w);
        }
        // stage B tile: 16x128, convert to tf32, guard n edge
#pragma unroll
        for (int i = 0; i < 2; i++) {
            int idx = tid * 2 + i;
            int row = idx >> 5, c4 = (idx & 31) * 4;
            int n = n0 + c4;
            float4 v = make_float4(0.f, 0.f, 0.f, 0.f);
            if (n < NPIX) v = *(const float4*)(B + (size_t)(k0 + row) * NPIX + n);
            uint32_t* d = &Bs[row * 136 + c4];
            d[0] = f2tf(v.x); d[1] = f2tf(v.y); d[2] = f2tf(v.z); d[3] = f2tf(v.w);
        }
        __syncthreads();

#pragma unroll
        for (int ks = 0; ks < 2; ks++) {
            int k = ks * 8;
            uint32_t af[4][4], bf[4][2];
#pragma unroll
            for (int mt = 0; mt < 4; mt++) {
                int r = wm + mt * 16 + (lane >> 2);
                int cc = k + (lane & 3);
                af[mt][0] = As[r * 20 + cc];
                af[mt][1] = As[(r + 8) * 20 + cc];
                af[mt][2] = As[r * 20 + cc + 4];
                af[mt][3] = As[(r + 8) * 20 + cc + 4];
            }
#pragma unroll
            for (int nt = 0; nt < 4; nt++) {
                int nn = wn + nt * 8 + (lane >> 2);
                bf[nt][0] = Bs[(k + (lane & 3)) * 136 + nn];
                bf[nt][1] = Bs[(k + 4 + (lane & 3)) * 136 + nn];
            }
#pragma unroll
            for (int mt = 0; mt < 4; mt++)
#pragma unroll
                for (int nt = 0; nt < 4; nt++)
                    mma_tf32(acc[mt][nt], af[mt], bf[nt]);
        }
        __syncthreads();
    }

    // windowed scatter store
    float* Out = g_qkv[pr] + (size_t)b * INNER * NPIX;
    int wwin[8], twin[8];
    bool nv[8];
#pragma unroll
    for (int nt = 0; nt < 4; nt++)
#pragma unroll
        for (int c = 0; c < 2; c++) {
            int id = nt * 2 + c;
            int n = n0 + wn + nt * 8 + (lane & 3) * 2 + c;
            nv[id] = (n < NPIX);
            int nn = nv[id] ? n : 0;
            int yy = nn / 56, xx = nn % 56;
            wwin[id] = (yy / 7) * 8 + (xx / 7);
            twin[id] = (yy % 7) * 7 + (xx % 7);
        }
#pragma unroll
    for (int mt = 0; mt < 4; mt++) {
#pragma unroll
        for (int rr = 0; rr < 2; rr++) {
            int m = m0 + wm + mt * 16 + (lane >> 2) + rr * 8;
            int h = m >> 6, d = m & 63;
#pragma unroll
            for (int nt = 0; nt < 4; nt++)
#pragma unroll
                for (int c = 0; c < 2; c++) {
                    int id = nt * 2 + c;
                    if (nv[id])
                        Out[(((size_t)h * NWIN + wwin[id]) * DHEAD + d) * NTOK + twin[id]]
                            = acc[mt][nt][rr * 2 + c];
                }
        }
    }
}

// ---------------------------------------------------------------------------
// Kernel E (tf32 tensor core): out[co,pix] = out_w[co,ci]*att[ci,pix] + bias
// Same tiling; K=512; plain coalesced output via float2.
// ---------------------------------------------------------------------------
__global__ void __launch_bounds__(256, 2) out_gemm_tc(
    const float* __restrict__ A, const float* __restrict__ ob,
    float* __restrict__ out)
{
    __shared__ uint32_t As[128 * 20];
    __shared__ uint32_t Bs[16 * 136];

    int nb = blockIdx.x;                 // 0..24
    int mb = blockIdx.y;                 // 0..1
    int b  = blockIdx.z;                 // 0..15
    const float* B = g_att + (size_t)b * INNER * NPIX;

    int tid = threadIdx.x;
    int lane = tid & 31, warp = tid >> 5;
    int wm = (warp & 1) * 64;
    int wn = (warp >> 1) * 32;
    int m0 = mb * 128, n0 = nb * 128;

    float acc[4][4][4];
#pragma unroll
    for (int mt = 0; mt < 4; mt++)
#pragma unroll
        for (int nt = 0; nt < 4; nt++)
#pragma unroll
            for (int i = 0; i < 4; i++) acc[mt][nt][i] = 0.f;

    for (int k0 = 0; k0 < INNER; k0 += 16) {
#pragma unroll
        for (int i = 0; i < 2; i++) {
            int idx = tid * 2 + i;
            int row = idx >> 2, k4 = (idx & 3) * 4;
            float4 v = *(const float4*)(A + (size_t)(m0 + row) * INNER + k0 + k4);
            uint32_t* d = &As[row * 20 + k4];
            d[0] = f2tf(v.x); d[1] = f2tf(v.y); d[2] = f2tf(v.z); d[3] = f2tf(v.w);
        }
#pragma unroll
        for (int i = 0; i < 2; i++) {
            int idx = tid * 2 + i;
            int row = idx >> 5, c4 = (idx & 31) * 4;
            int n = n0 + c4;
            float4 v = make_float4(0.f, 0.f, 0.f, 0.f);
            if (n < NPIX) v = *(const float4*)(B + (size_t)(k0 + row) * NPIX + n);
            uint32_t* d = &Bs[row * 136 + c4];
            d[0] = f2tf(v.x); d[1] = f2tf(v.y); d[2] = f2tf(v.z); d[3] = f2tf(v.w);
        }
        __syncthreads();

#pragma unroll
        for (int ks = 0; ks < 2; ks++) {
            int k = ks * 8;
            uint32_t af[4][4], bf[4][2];
#pragma unroll
            for (int mt = 0; mt < 4; mt++) {
                int r = wm + mt * 16 + (lane >> 2);
                int cc = k + (lane & 3);
                af[mt][0] = As[r * 20 + cc];
                af[mt][1] = As[(r + 8) * 20 + cc];
                af[mt][2] = As[r * 20 + cc + 4];
                af[mt][3] = As[(r + 8) * 20 + cc + 4];
            }
#pragma unroll
            for (int nt = 0; nt < 4; nt++) {
                int nn = wn + nt * 8 + (lane >> 2);
                bf[nt][0] = Bs[(k + (lane & 3)) * 136 + nn];
                bf[nt][1] = Bs[(k + 4 + (lane & 3)) * 136 + nn];
            }
#pragma unroll
            for (int mt = 0; mt < 4; mt++)
#pragma unroll
                for (int nt = 0; nt < 4; nt++)
                    mma_tf32(acc[mt][nt], af[mt], bf[nt]);
        }
        __syncthreads();
    }

#pragma unroll
    for (int mt = 0; mt < 4; mt++) {
#pragma unroll
        for (int rr = 0; rr < 2; rr++) {
            int m = m0 + wm + mt * 16 + (lane >> 2) + rr * 8;
            float bias = __ldg(ob + m);
#pragma unroll
            for (int nt = 0; nt < 4; nt++) {
                int n = n0 + wn + nt * 8 + (lane & 3) * 2;
                if (n < NPIX) {
                    float2 v;
                    v.x = acc[mt][nt][rr * 2 + 0] + bias;
                    v.y = acc[mt][nt][rr * 2 + 1] + bias;
                    *(float2*)&out[(size_t)(b * DIM + m) * NPIX + n] = v;
                }
            }
        }
    }
}

// ---------------------------------------------------------------------------
// Kernel D: windowed attention (fp32). One CTA per (b, h, w).
// ---------------------------------------------------------------------------
__global__ void __launch_bounds__(256) attn_kernel() {
    __shared__ float qs[64 * 52 + 16];  // [kk][t] stride 52; later aliased as attnT [j][i] stride 68
    __shared__ float ks[64 * 52 + 16];  // [kk][t] stride 52
    __shared__ float vs[64 * 49];       // [d][t]
    __shared__ float dots[49 * 50];     // [i][j] stride 50

    int w = blockIdx.x, h = blockIdx.y, b = blockIdx.z;
    int tid = threadIdx.x;
    size_t base = ((size_t)(b * HEADS + h) * NWIN + w) * (DHEAD * NTOK);
    const float* qg = g_qkv[0] + base;
    const float* kg = g_qkv[1] + base;
    const float* vg = g_qkv[2] + base;

    for (int idx = tid; idx < DHEAD * NTOK; idx += 256) {
        int dd = idx / NTOK, t = idx - dd * NTOK;
        qs[dd * 52 + t] = qg[idx];
        ks[dd * 52 + t] = kg[idx];
        vs[idx] = vg[idx];
    }
    __syncthreads();

    int tx = tid & 15, ty = tid >> 4;

    float acc[4][4];
#pragma unroll
    for (int i = 0; i < 4; i++)
#pragma unroll
        for (int j = 0; j < 4; j++) acc[i][j] = 0.f;

#pragma unroll 8
    for (int kk = 0; kk < 64; kk++) {
        float a[4], bb[4];
        *(float4*)a  = *(const float4*)&qs[kk * 52 + ty * 4];
        *(float4*)bb = *(const float4*)&ks[kk * 52 + tx * 4];
#pragma unroll
        for (int mm = 0; mm < 4; mm++)
#pragma unroll
            for (int nn = 0; nn < 4; nn++)
                acc[mm][nn] += a[mm] * bb[nn];
    }

    const float* bptr = g_bias + h * NTOK * NTOK;
#pragma unroll
    for (int mm = 0; mm < 4; mm++) {
        int i = ty * 4 + mm;
        if (i < NTOK) {
#pragma unroll
            for (int nn = 0; nn < 4; nn++) {
                int j = tx * 4 + nn;
                if (j < NTOK)
                    dots[i * 50 + j] = acc[mm][nn] * 0.125f + __ldg(bptr + i * NTOK + j);
            }
        }
    }
    __syncthreads();

    float* attnT = qs;  // q tile dead from here on
    int warp = tid >> 5, lane = tid & 31;
    for (int i = warp; i < NTOK; i += 8) {
        float v1 = dots[i * 50 + lane];
        float v2 = (lane + 32 < NTOK) ? dots[i * 50 + lane + 32] : -1e30f;
        float mx = fmaxf(v1, v2);
#pragma unroll
        for (int o = 16; o > 0; o >>= 1) mx = fmaxf(mx, __shfl_xor_sync(0xffffffffu, mx, o));
        float e1 = __expf(v1 - mx);
        float e2 = (lane + 32 < NTOK) ? __expf(v2 - mx) : 0.f;
        float s = e1 + e2;
#pragma unroll
        for (int o = 16; o > 0; o >>= 1) s += __shfl_xor_sync(0xffffffffu, s, o);
        float inv = 1.f / s;
        attnT[lane * 68 + i] = e1 * inv;
        if (lane + 32 < NTOK) attnT[(lane + 32) * 68 + i] = e2 * inv;
    }
    __syncthreads();

    float o[4][4];
#pragma unroll
    for (int i = 0; i < 4; i++)
#pragma unroll
        for (int j = 0; j < 4; j++) o[i][j] = 0.f;

#pragma unroll 7
    for (int j = 0; j < NTOK; j++) {
        float a[4], bb[4];
#pragma unroll
        for (int mm = 0; mm < 4; mm++) a[mm] = vs[(ty * 4 + mm) * NTOK + j];
        *(float4*)bb = *(const float4*)&attnT[j * 68 + tx * 4];
#pragma unroll
        for (int mm = 0; mm < 4; mm++)
#pragma unroll
            for (int nn = 0; nn < 4; nn++)
                o[mm][nn] += a[mm] * bb[nn];
    }

    int nh = w >> 3, nw2 = w & 7;
    float* outp = g_att + (size_t)b * INNER * NPIX + (size_t)h * DHEAD * NPIX;
#pragma unroll
    for (int nn = 0; nn < 4; nn++) {
        int i = tx * 4 + nn;
        if (i < NTOK) {
            int yy = nh * 7 + i / 7;
            int xx = nw2 * 7 + i % 7;
            int poff = yy * 56 + xx;
#pragma unroll
            for (int mm = 0; mm < 4; mm++) {
                int d = ty * 4 + mm;
                outp[(size_t)d * NPIX + poff] = o[mm][nn];
            }
        }
    }
}

// ---------------------------------------------------------------------------
extern "C" void kernel_launch(void* const* d_in, const int* in_sizes, int n_in,
                              void* d_out, int out_size) {
    const float* x   = (const float*)d_in[0];
    const float* qdw = (const float*)d_in[1];
    const float* qg  = (const float*)d_in[2];
    const float* qb  = (const float*)d_in[3];
    const float* qm  = (const float*)d_in[4];
    const float* qv  = (const float*)d_in[5];
    const float* qpw = (const float*)d_in[6];
    const float* kdw = (const float*)d_in[7];
    const float* kg  = (const float*)d_in[8];
    const float* kb  = (const float*)d_in[9];
    const float* km  = (const float*)d_in[10];
    const float* kv  = (const float*)d_in[11];
    const float* kpw = (const float*)d_in[12];
    const float* vdw = (const float*)d_in[13];
    const float* vg  = (const float*)d_in[14];
    const float* vb  = (const float*)d_in[15];
    const float* vm  = (const float*)d_in[16];
    const float* vv  = (const float*)d_in[17];
    const float* vpw = (const float*)d_in[18];
    const float* pos = (const float*)d_in[19];
    const float* ow  = (const float*)d_in[20];
    const float* obias = (const float*)d_in[21];
    float* out = (float*)d_out;

    bias_kernel<<<(HEADS * NTOK * NTOK + 255) / 256, 256>>>(pos);

    dwbn_kernel<<<dim3((NPIX + 255) / 256, BATCH * DIM), 256>>>(
        x, qdw, qg, qb, qm, qv, kdw, kg, kb, km, kv, vdw, vg, vb, vm, vv);

    proj_gemm_tc<<<dim3(25, 4, BATCH * 3), 256>>>(qpw, kpw, vpw);

    attn_kernel<<<dim3(NWIN, HEADS, BATCH), 256>>>();

    out_gemm_tc<<<dim3(25, 2, BATCH), 256>>>(ow, obias, out);
}

// round 3
// speedup vs baseline: 2.0189x; 1.8207x over previous
#include <cuda_runtime.h>
#include <math.h>
#include <stdint.h>

#define DIM    256
#define INNER  512
#define HEADS  8
#define DHEAD  64
#define NTOK   49
#define NPIX   3136
#define BATCH  16
#define NWIN   64
#define EPS    1e-5f

// Scratch (allocation-free: __device__ globals)
__device__ float g_y[3][BATCH * DIM * NPIX];      // dwconv+BN outputs (q,k,v): [b][c][pix]
__device__ float g_qkv[3][BATCH * INNER * NPIX];  // projected, PLAIN layout: [b][c][pix]
__device__ float g_att[BATCH * INNER * NPIX];     // attention out, plain: [b][ci][y][x]
__device__ float g_bias[HEADS * NTOK * NTOK];     // rel-pos bias: [h][i][j]

// ---------------------------------------------------------------------------
// tf32 helpers
// ---------------------------------------------------------------------------
__device__ __forceinline__ uint32_t f2tf(float f) {
    uint32_t u;
    asm("cvt.rna.tf32.f32 %0, %1;" : "=r"(u) : "f"(f));
    return u;
}

__device__ __forceinline__ void mma_tf32(float c[4], const uint32_t a[4], const uint32_t b[2]) {
    asm volatile(
        "mma.sync.aligned.m16n8k8.row.col.f32.tf32.tf32.f32 "
        "{%0,%1,%2,%3}, {%4,%5,%6,%7}, {%8,%9}, {%0,%1,%2,%3};\n"
        : "+f"(c[0]), "+f"(c[1]), "+f"(c[2]), "+f"(c[3])
        : "r"(a[0]), "r"(a[1]), "r"(a[2]), "r"(a[3]), "r"(b[0]), "r"(b[1]));
}

// ---------------------------------------------------------------------------
// Kernel C: precompute relative position bias table [h][i][j]
// ---------------------------------------------------------------------------
__global__ void bias_kernel(const float* __restrict__ pos) {
    int idx = blockIdx.x * 256 + threadIdx.x;
    if (idx >= HEADS * NTOK * NTOK) return;
    int h = idx / (NTOK * NTOK);
    int r = idx % (NTOK * NTOK);
    int i = r / NTOK, j = r % NTOK;
    int xi = i / 7, yi = i % 7, xj = j / 7, yj = j % 7;
    int rel = (xj - xi + 6) * 13 + (yj - yi + 6);
    g_bias[idx] = __ldg(pos + rel * HEADS + h);
}

// ---------------------------------------------------------------------------
// Kernel A: depthwise 3x3 conv + BN (eval) for all 3 projections, x read once
// ---------------------------------------------------------------------------
__global__ void __launch_bounds__(256) dwbn_kernel(
    const float* __restrict__ x,
    const float* __restrict__ dwq, const float* __restrict__ gq, const float* __restrict__ bq,
    const float* __restrict__ mq,  const float* __restrict__ vq,
    const float* __restrict__ dwk, const float* __restrict__ gk, const float* __restrict__ bk,
    const float* __restrict__ mk,  const float* __restrict__ vk,
    const float* __restrict__ dwv, const float* __restrict__ gv, const float* __restrict__ bv,
    const float* __restrict__ mv,  const float* __restrict__ vv)
{
    int p = blockIdx.x * 256 + threadIdx.x;
    if (p >= NPIX) return;
    int bc = blockIdx.y;            // b*256 + c
    int c  = bc & (DIM - 1);
    const float* xp = x + (size_t)bc * NPIX;
    int y0 = p / 56, x0 = p % 56;

    float t[9];
#pragma unroll
    for (int dy = 0; dy < 3; dy++)
#pragma unroll
        for (int dx = 0; dx < 3; dx++) {
            int yy = y0 + dy - 1, xx = x0 + dx - 1;
            t[dy * 3 + dx] = (yy >= 0 && yy < 56 && xx >= 0 && xx < 56)
                           ? __ldg(xp + yy * 56 + xx) : 0.f;
        }

    const float* DW[3] = {dwq, dwk, dwv};
    const float* GG[3] = {gq, gk, gv};
    const float* BB[3] = {bq, bk, bv};
    const float* MM[3] = {mq, mk, mv};
    const float* VV[3] = {vq, vk, vv};

#pragma unroll
    for (int pr = 0; pr < 3; pr++) {
        float acc = 0.f;
        const float* wp = DW[pr] + c * 9;
#pragma unroll
        for (int j = 0; j < 9; j++) acc += t[j] * __ldg(wp + j);
        float sc = __ldg(GG[pr] + c) * rsqrtf(__ldg(VV[pr] + c) + EPS);
        float sh = __ldg(BB[pr] + c) - __ldg(MM[pr] + c) * sc;
        g_y[pr][(size_t)bc * NPIX + p] = acc * sc + sh;
    }
}

// ---------------------------------------------------------------------------
// Kernel B (tf32 tensor core): proj GEMM out[inner, pix] = pw[inner,c]*y[c,pix]
// BM=128, BN=128, BK=16; 8 warps (2x4), warp tile 64x32; mma.m16n8k8 tf32.
// Writes plain [b][inner][pix], coalesced float2.
// ---------------------------------------------------------------------------
__global__ void __launch_bounds__(256, 2) proj_gemm_tc(
    const float* __restrict__ pw0, const float* __restrict__ pw1,
    const float* __restrict__ pw2)
{
    __shared__ uint32_t As[128 * 20];   // [m][k] stride 20
    __shared__ uint32_t Bs[16 * 136];   // [k][n] stride 136

    int nb = blockIdx.x;                 // 0..24
    int mb = blockIdx.y;                 // 0..3
    int bz = blockIdx.z;                 // b*3 + proj
    int pr = bz % 3, b = bz / 3;
    const float* A = (pr == 0) ? pw0 : ((pr == 1) ? pw1 : pw2);
    const float* B = g_y[pr] + (size_t)b * DIM * NPIX;

    int tid = threadIdx.x;
    int lane = tid & 31, warp = tid >> 5;
    int wm = (warp & 1) * 64;
    int wn = (warp >> 1) * 32;
    int m0 = mb * 128, n0 = nb * 128;

    float acc[4][4][4];
#pragma unroll
    for (int mt = 0; mt < 4; mt++)
#pragma unroll
        for (int nt = 0; nt < 4; nt++)
#pragma unroll
            for (int i = 0; i < 4; i++) acc[mt][nt][i] = 0.f;

    for (int k0 = 0; k0 < DIM; k0 += 16) {
#pragma unroll
        for (int i = 0; i < 2; i++) {
            int idx = tid * 2 + i;
            int row = idx >> 2, k4 = (idx & 3) * 4;
            float4 v = *(const float4*)(A + (size_t)(m0 + row) * DIM + k0 + k4);
            uint32_t* d = &As[row * 20 + k4];
            d[0] = f2tf(v.x); d[1] = f2tf(v.y); d[2] = f2tf(v.z); d[3] = f2tf(v.w);
        }
#pragma unroll
        for (int i = 0; i < 2; i++) {
            int idx = tid * 2 + i;
            int row = idx >> 5, c4 = (idx & 31) * 4;
            int n = n0 + c4;
            float4 v = make_float4(0.f, 0.f, 0.f, 0.f);
            if (n < NPIX) v = *(const float4*)(B + (size_t)(k0 + row) * NPIX + n);
            uint32_t* d = &Bs[row * 136 + c4];
            d[0] = f2tf(v.x); d[1] = f2tf(v.y); d[2] = f2tf(v.z); d[3] = f2tf(v.w);
        }
        __syncthreads();

#pragma unroll
        for (int ks = 0; ks < 2; ks++) {
            int k = ks * 8;
            uint32_t af[4][4], bf[4][2];
#pragma unroll
            for (int mt = 0; mt < 4; mt++) {
                int r = wm + mt * 16 + (lane >> 2);
                int cc = k + (lane & 3);
                af[mt][0] = As[r * 20 + cc];
                af[mt][1] = As[(r + 8) * 20 + cc];
                af[mt][2] = As[r * 20 + cc + 4];
                af[mt][3] = As[(r + 8) * 20 + cc + 4];
            }
#pragma unroll
            for (int nt = 0; nt < 4; nt++) {
                int nn = wn + nt * 8 + (lane >> 2);
                bf[nt][0] = Bs[(k + (lane & 3)) * 136 + nn];
                bf[nt][1] = Bs[(k + 4 + (lane & 3)) * 136 + nn];
            }
#pragma unroll
            for (int mt = 0; mt < 4; mt++)
#pragma unroll
                for (int nt = 0; nt < 4; nt++)
                    mma_tf32(acc[mt][nt], af[mt], bf[nt]);
        }
        __syncthreads();
    }

    float* Out = g_qkv[pr] + (size_t)b * INNER * NPIX;
#pragma unroll
    for (int mt = 0; mt < 4; mt++) {
#pragma unroll
        for (int rr = 0; rr < 2; rr++) {
            int m = m0 + wm + mt * 16 + (lane >> 2) + rr * 8;
#pragma unroll
            for (int nt = 0; nt < 4; nt++) {
                int n = n0 + wn + nt * 8 + (lane & 3) * 2;
                if (n < NPIX) {
                    float2 v;
                    v.x = acc[mt][nt][rr * 2 + 0];
                    v.y = acc[mt][nt][rr * 2 + 1];
                    *(float2*)&Out[(size_t)m * NPIX + n] = v;
                }
            }
        }
    }
}

// ---------------------------------------------------------------------------
// Kernel E (tf32 tensor core): out[co,pix] = out_w[co,ci]*att[ci,pix] + bias
// ---------------------------------------------------------------------------
__global__ void __launch_bounds__(256, 2) out_gemm_tc(
    const float* __restrict__ A, const float* __restrict__ ob,
    float* __restrict__ out)
{
    __shared__ uint32_t As[128 * 20];
    __shared__ uint32_t Bs[16 * 136];

    int nb = blockIdx.x;                 // 0..24
    int mb = blockIdx.y;                 // 0..1
    int b  = blockIdx.z;                 // 0..15
    const float* B = g_att + (size_t)b * INNER * NPIX;

    int tid = threadIdx.x;
    int lane = tid & 31, warp = tid >> 5;
    int wm = (warp & 1) * 64;
    int wn = (warp >> 1) * 32;
    int m0 = mb * 128, n0 = nb * 128;

    float acc[4][4][4];
#pragma unroll
    for (int mt = 0; mt < 4; mt++)
#pragma unroll
        for (int nt = 0; nt < 4; nt++)
#pragma unroll
            for (int i = 0; i < 4; i++) acc[mt][nt][i] = 0.f;

    for (int k0 = 0; k0 < INNER; k0 += 16) {
#pragma unroll
        for (int i = 0; i < 2; i++) {
            int idx = tid * 2 + i;
            int row = idx >> 2, k4 = (idx & 3) * 4;
            float4 v = *(const float4*)(A + (size_t)(m0 + row) * INNER + k0 + k4);
            uint32_t* d = &As[row * 20 + k4];
            d[0] = f2tf(v.x); d[1] = f2tf(v.y); d[2] = f2tf(v.z); d[3] = f2tf(v.w);
        }
#pragma unroll
        for (int i = 0; i < 2; i++) {
            int idx = tid * 2 + i;
            int row = idx >> 5, c4 = (idx & 31) * 4;
            int n = n0 + c4;
            float4 v = make_float4(0.f, 0.f, 0.f, 0.f);
            if (n < NPIX) v = *(const float4*)(B + (size_t)(k0 + row) * NPIX + n);
            uint32_t* d = &Bs[row * 136 + c4];
            d[0] = f2tf(v.x); d[1] = f2tf(v.y); d[2] = f2tf(v.z); d[3] = f2tf(v.w);
        }
        __syncthreads();

#pragma unroll
        for (int ks = 0; ks < 2; ks++) {
            int k = ks * 8;
            uint32_t af[4][4], bf[4][2];
#pragma unroll
            for (int mt = 0; mt < 4; mt++) {
                int r = wm + mt * 16 + (lane >> 2);
                int cc = k + (lane & 3);
                af[mt][0] = As[r * 20 + cc];
                af[mt][1] = As[(r + 8) * 20 + cc];
                af[mt][2] = As[r * 20 + cc + 4];
                af[mt][3] = As[(r + 8) * 20 + cc + 4];
            }
#pragma unroll
            for (int nt = 0; nt < 4; nt++) {
                int nn = wn + nt * 8 + (lane >> 2);
                bf[nt][0] = Bs[(k + (lane & 3)) * 136 + nn];
                bf[nt][1] = Bs[(k + 4 + (lane & 3)) * 136 + nn];
            }
#pragma unroll
            for (int mt = 0; mt < 4; mt++)
#pragma unroll
                for (int nt = 0; nt < 4; nt++)
                    mma_tf32(acc[mt][nt], af[mt], bf[nt]);
        }
        __syncthreads();
    }

#pragma unroll
    for (int mt = 0; mt < 4; mt++) {
#pragma unroll
        for (int rr = 0; rr < 2; rr++) {
            int m = m0 + wm + mt * 16 + (lane >> 2) + rr * 8;
            float bias = __ldg(ob + m);
#pragma unroll
            for (int nt = 0; nt < 4; nt++) {
                int n = n0 + wn + nt * 8 + (lane & 3) * 2;
                if (n < NPIX) {
                    float2 v;
                    v.x = acc[mt][nt][rr * 2 + 0] + bias;
                    v.y = acc[mt][nt][rr * 2 + 1] + bias;
                    *(float2*)&out[(size_t)(b * DIM + m) * NPIX + n] = v;
                }
            }
        }
    }
}

// ---------------------------------------------------------------------------
// Kernel D (tf32 tensor core): windowed attention. One CTA per (b, h, w).
// QK^T: M=64(i pad), N=56(j pad), K=64(d).   A=qs[t][d](s68)  B=ks[t][d](s68)
// AV  : outT = V attn^T. M=64(d), N=64(i pad), K=56(j pad).
//       A=vs[d][t](s60, t 49..55 zeroed)  B=attnS[i][j](s68, j 49..55 zeroed)
// attnS aliases the dead Q tile. smem = 48,000 B.
// ---------------------------------------------------------------------------
__global__ void __launch_bounds__(256) attn_tc() {
    __shared__ uint32_t qs[64 * 68];   // Q tf32 [t][d]; later attnS (float) [i][j]
    __shared__ uint32_t ks[56 * 68];   // K tf32 [t][d]
    __shared__ uint32_t vs[64 * 60];   // V tf32 [d][t]

    int w = blockIdx.x, h = blockIdx.y, b = blockIdx.z;
    int tid = threadIdx.x, lane = tid & 31, warp = tid >> 5;
    int nh = w >> 3, nw2 = w & 7;
    int px0 = (nh * 7) * 56 + nw2 * 7;

    size_t cbase = ((size_t)b * INNER + h * DHEAD) * NPIX;
    const float* qg = g_qkv[0] + cbase;
    const float* kg = g_qkv[1] + cbase;
    const float* vg = g_qkv[2] + cbase;

    // gather window (7-float contiguous chunks), convert to tf32 once
    for (int idx = tid; idx < DHEAD * NTOK; idx += 256) {
        int d = idx / NTOK, t = idx - d * NTOK;
        int poff = px0 + (t / 7) * 56 + (t % 7);
        size_t g = (size_t)d * NPIX + poff;
        qs[t * 68 + d] = f2tf(__ldg(qg + g));
        ks[t * 68 + d] = f2tf(__ldg(kg + g));
        vs[d * 60 + t] = f2tf(__ldg(vg + g));
    }
    // zero V pad columns t = 49..55 (AV K pad)
    for (int idx = tid; idx < DHEAD * 7; idx += 256) {
        int d = idx / 7, t = NTOK + idx % 7;
        vs[d * 60 + t] = 0u;
    }
    __syncthreads();

    int wm = (warp >> 1) * 16;          // m16 tile (i for QK, d for AV)
    int wn = (warp & 1) * 32;           // n half
    int ntmaxQK = (warp & 1) ? 3 : 4;   // N=56 for QK

    // ---- QK^T
    float acc[4][4];
#pragma unroll
    for (int nt = 0; nt < 4; nt++)
#pragma unroll
        for (int i = 0; i < 4; i++) acc[nt][i] = 0.f;

#pragma unroll
    for (int ks8 = 0; ks8 < 8; ks8++) {
        int k0 = ks8 * 8;
        int r = wm + (lane >> 2), kk = k0 + (lane & 3);
        uint32_t af[4];
        af[0] = qs[r * 68 + kk];
        af[1] = qs[(r + 8) * 68 + kk];
        af[2] = qs[r * 68 + kk + 4];
        af[3] = qs[(r + 8) * 68 + kk + 4];
#pragma unroll
        for (int nt = 0; nt < 4; nt++) {
            if (nt < ntmaxQK) {
                int n = wn + nt * 8 + (lane >> 2);
                uint32_t bf[2];
                bf[0] = ks[n * 68 + kk];
                bf[1] = ks[n * 68 + kk + 4];
                mma_tf32(acc[nt], af, bf);
            }
        }
    }
    __syncthreads();  // all warps done reading qs before aliasing

    // ---- write dots (+bias) into attnS (alias of qs)
    float* attnS = (float*)qs;
    const float* bptr = g_bias + h * NTOK * NTOK;
#pragma unroll
    for (int nt = 0; nt < 4; nt++) {
        if (nt < ntmaxQK) {
#pragma unroll
            for (int rr = 0; rr < 2; rr++) {
                int i = wm + (lane >> 2) + rr * 8;
                if (i < NTOK) {
#pragma unroll
                    for (int c = 0; c < 2; c++) {
                        int j = wn + nt * 8 + (lane & 3) * 2 + c;
                        if (j < NTOK)
                            attnS[i * 68 + j] = acc[nt][rr * 2 + c] * 0.125f
                                              + __ldg(bptr + i * NTOK + j);
                    }
                }
            }
        }
    }
    __syncthreads();

    // ---- softmax: warp per row; zeros written into j = 49..63
    for (int i = warp; i < NTOK; i += 8) {
        float v1 = attnS[i * 68 + lane];
        float v2 = (lane + 32 < NTOK) ? attnS[i * 68 + lane + 32] : -1e30f;
        float mx = fmaxf(v1, v2);
#pragma unroll
        for (int o = 16; o > 0; o >>= 1) mx = fmaxf(mx, __shfl_xor_sync(0xffffffffu, mx, o));
        float e1 = __expf(v1 - mx);
        float e2 = (lane + 32 < NTOK) ? __expf(v2 - mx) : 0.f;
        float s = e1 + e2;
#pragma unroll
        for (int o = 16; o > 0; o >>= 1) s += __shfl_xor_sync(0xffffffffu, s, o);
        float inv = 1.f / s;
        attnS[i * 68 + lane] = e1 * inv;
        attnS[i * 68 + lane + 32] = (lane + 32 < NTOK) ? e2 * inv : 0.f;
    }
    __syncthreads();

    // ---- AV: outT[d][i] = sum_j V[d][j] * attn[i][j]
    float acc2[4][4];
#pragma unroll
    for (int nt = 0; nt < 4; nt++)
#pragma unroll
        for (int i = 0; i < 4; i++) acc2[nt][i] = 0.f;

#pragma unroll
    for (int ks8 = 0; ks8 < 7; ks8++) {
        int k0 = ks8 * 8;
        int r = wm + (lane >> 2), kk = k0 + (lane & 3);
        uint32_t af[4];
        af[0] = vs[r * 60 + kk];
        af[1] = vs[(r + 8) * 60 + kk];
        af[2] = vs[r * 60 + kk + 4];
        af[3] = vs[(r + 8) * 60 + kk + 4];
#pragma unroll
        for (int nt = 0; nt < 4; nt++) {
            int n = wn + nt * 8 + (lane >> 2);
            uint32_t bf[2];
            bf[0] = f2tf(attnS[n * 68 + kk]);
            bf[1] = f2tf(attnS[n * 68 + kk + 4]);
            mma_tf32(acc2[nt], af, bf);
        }
    }

    // ---- store (un-window): plain [b][ci][y][x]
    float* outp = g_att + (size_t)b * INNER * NPIX + (size_t)h * DHEAD * NPIX;
#pragma unroll
    for (int nt = 0; nt < 4; nt++) {
#pragma unroll
        for (int c = 0; c < 2; c++) {
            int i = wn + nt * 8 + (lane & 3) * 2 + c;
            if (i < NTOK) {
                int poff = px0 + (i / 7) * 56 + (i % 7);
#pragma unroll
                for (int rr = 0; rr < 2; rr++) {
                    int d = wm + (lane >> 2) + rr * 8;
                    outp[(size_t)d * NPIX + poff] = acc2[nt][rr * 2 + c];
                }
            }
        }
    }
}

// ---------------------------------------------------------------------------
extern "C" void kernel_launch(void* const* d_in, const int* in_sizes, int n_in,
                              void* d_out, int out_size) {
    const float* x   = (const float*)d_in[0];
    const float* qdw = (const float*)d_in[1];
    const float* qg  = (const float*)d_in[2];
    const float* qb  = (const float*)d_in[3];
    const float* qm  = (const float*)d_in[4];
    const float* qv  = (const float*)d_in[5];
    const float* qpw = (const float*)d_in[6];
    const float* kdw = (const float*)d_in[7];
    const float* kg  = (const float*)d_in[8];
    const float* kb  = (const float*)d_in[9];
    const float* km  = (const float*)d_in[10];
    const float* kv  = (const float*)d_in[11];
    const float* kpw = (const float*)d_in[12];
    const float* vdw = (const float*)d_in[13];
    const float* vg  = (const float*)d_in[14];
    const float* vb  = (const float*)d_in[15];
    const float* vm  = (const float*)d_in[16];
    const float* vv  = (const float*)d_in[17];
    const float* vpw = (const float*)d_in[18];
    const float* pos = (const float*)d_in[19];
    const float* ow  = (const float*)d_in[20];
    const float* obias = (const float*)d_in[21];
    float* out = (float*)d_out;

    bias_kernel<<<(HEADS * NTOK * NTOK + 255) / 256, 256>>>(pos);

    dwbn_kernel<<<dim3((NPIX + 255) / 256, BATCH * DIM), 256>>>(
        x, qdw, qg, qb, qm, qv, kdw, kg, kb, km, kv, vdw, vg, vb, vm, vv);

    proj_gemm_tc<<<dim3(25, 4, BATCH * 3), 256>>>(qpw, kpw, vpw);

    attn_tc<<<dim3(NWIN, HEADS, BATCH), 256>>>();

    out_gemm_tc<<<dim3(25, 2, BATCH), 256>>>(ow, obias, out);
}

// round 5
// speedup vs baseline: 2.1200x; 1.0501x over previous
#include <cuda_runtime.h>
#include <math.h>
#include <stdint.h>

#define DIM    256
#define INNER  512
#define HEADS  8
#define DHEAD  64
#define NTOK   49
#define NPIX   3136
#define BATCH  16
#define NWIN   64
#define EPS    1e-5f

// Scratch (allocation-free: __device__ globals)
__device__ float g_y[3][BATCH * DIM * NPIX];      // dwconv+BN outputs (q,k,v): [b][c][pix]
__device__ float g_qkv[3][BATCH * INNER * NPIX];  // projected, PLAIN layout: [b][c][pix]
__device__ float g_att[BATCH * INNER * NPIX];     // attention out, plain: [b][ci][y][x]
__device__ float g_bias[HEADS * NTOK * NTOK];     // rel-pos bias: [h][i][j]

// ---------------------------------------------------------------------------
// tf32 helpers
// ---------------------------------------------------------------------------
__device__ __forceinline__ uint32_t f2tf(float f) {
    uint32_t u;
    asm("cvt.rna.tf32.f32 %0, %1;" : "=r"(u) : "f"(f));
    return u;
}

__device__ __forceinline__ void mma_tf32(float c[4], const uint32_t a[4], const uint32_t b[2]) {
    asm volatile(
        "mma.sync.aligned.m16n8k8.row.col.f32.tf32.tf32.f32 "
        "{%0,%1,%2,%3}, {%4,%5,%6,%7}, {%8,%9}, {%0,%1,%2,%3};\n"
        : "+f"(c[0]), "+f"(c[1]), "+f"(c[2]), "+f"(c[3])
        : "r"(a[0]), "r"(a[1]), "r"(a[2]), "r"(a[3]), "r"(b[0]), "r"(b[1]));
}

// ---------------------------------------------------------------------------
// Kernel C: precompute relative position bias table [h][i][j]
// ---------------------------------------------------------------------------
__global__ void bias_kernel(const float* __restrict__ pos) {
    int idx = blockIdx.x * 256 + threadIdx.x;
    if (idx >= HEADS * NTOK * NTOK) return;
    int h = idx / (NTOK * NTOK);
    int r = idx % (NTOK * NTOK);
    int i = r / NTOK, j = r % NTOK;
    int xi = i / 7, yi = i % 7, xj = j / 7, yj = j % 7;
    int rel = (xj - xi + 6) * 13 + (yj - yi + 6);
    g_bias[idx] = __ldg(pos + rel * HEADS + h);
}

// ---------------------------------------------------------------------------
// Kernel A: depthwise 3x3 conv + BN (eval) for all 3 projections, x read once
// ---------------------------------------------------------------------------
__global__ void __launch_bounds__(256) dwbn_kernel(
    const float* __restrict__ x,
    const float* __restrict__ dwq, const float* __restrict__ gq, const float* __restrict__ bq,
    const float* __restrict__ mq,  const float* __restrict__ vq,
    const float* __restrict__ dwk, const float* __restrict__ gk, const float* __restrict__ bk,
    const float* __restrict__ mk,  const float* __restrict__ vk,
    const float* __restrict__ dwv, const float* __restrict__ gv, const float* __restrict__ bv,
    const float* __restrict__ mv,  const float* __restrict__ vv)
{
    int p = blockIdx.x * 256 + threadIdx.x;
    if (p >= NPIX) return;
    int bc = blockIdx.y;            // b*256 + c
    int c  = bc & (DIM - 1);
    const float* xp = x + (size_t)bc * NPIX;
    int y0 = p / 56, x0 = p % 56;

    float t[9];
#pragma unroll
    for (int dy = 0; dy < 3; dy++)
#pragma unroll
        for (int dx = 0; dx < 3; dx++) {
            int yy = y0 + dy - 1, xx = x0 + dx - 1;
            t[dy * 3 + dx] = (yy >= 0 && yy < 56 && xx >= 0 && xx < 56)
                           ? __ldg(xp + yy * 56 + xx) : 0.f;
        }

    const float* DW[3] = {dwq, dwk, dwv};
    const float* GG[3] = {gq, gk, gv};
    const float* BB[3] = {bq, bk, bv};
    const float* MM[3] = {mq, mk, mv};
    const float* VV[3] = {vq, vk, vv};

#pragma unroll
    for (int pr = 0; pr < 3; pr++) {
        float acc = 0.f;
        const float* wp = DW[pr] + c * 9;
#pragma unroll
        for (int j = 0; j < 9; j++) acc += t[j] * __ldg(wp + j);
        float sc = __ldg(GG[pr] + c) * rsqrtf(__ldg(VV[pr] + c) + EPS);
        float sh = __ldg(BB[pr] + c) - __ldg(MM[pr] + c) * sc;
        g_y[pr][(size_t)bc * NPIX + p] = acc * sc + sh;
    }
}

// ---------------------------------------------------------------------------
// Kernel B (tf32 TC, double-buffered): proj GEMM out[inner,pix]=pw*y
// BM=128, BN=128, BK=16; 8 warps (2x4), warp tile 64x32.
// Register prefetch of stage s+1 overlaps MMA on stage s; 1 barrier/stage.
// ---------------------------------------------------------------------------
__global__ void __launch_bounds__(256, 2) proj_gemm_tc(
    const float* __restrict__ pw0, const float* __restrict__ pw1,
    const float* __restrict__ pw2)
{
    __shared__ uint32_t As[2][128 * 20];
    __shared__ uint32_t Bs[2][16 * 136];

    int nb = blockIdx.x;                 // 0..24
    int mb = blockIdx.y;                 // 0..3
    int bz = blockIdx.z;                 // b*3 + proj
    int pr = bz % 3, b = bz / 3;
    const float* A = (pr == 0) ? pw0 : ((pr == 1) ? pw1 : pw2);
    const float* B = g_y[pr] + (size_t)b * DIM * NPIX;

    int tid = threadIdx.x;
    int lane = tid & 31, warp = tid >> 5;
    int wm = (warp & 1) * 64;
    int wn = (warp >> 1) * 32;
    int m0 = mb * 128, n0 = nb * 128;

    // per-thread load coords (fixed across stages)
    int aRow0 = (tid * 2) >> 2,     aK0 = ((tid * 2) & 3) * 4;
    int aRow1 = (tid * 2 + 1) >> 2, aK1 = ((tid * 2 + 1) & 3) * 4;
    int bRow0 = (tid * 2) >> 5,     bC0 = ((tid * 2) & 31) * 4;
    int bRow1 = (tid * 2 + 1) >> 5, bC1 = ((tid * 2 + 1) & 31) * 4;
    bool bOk0 = (n0 + bC0) < NPIX, bOk1 = (n0 + bC1) < NPIX;

    float acc[4][4][4];
#pragma unroll
    for (int mt = 0; mt < 4; mt++)
#pragma unroll
        for (int nt = 0; nt < 4; nt++)
#pragma unroll
            for (int i = 0; i < 4; i++) acc[mt][nt][i] = 0.f;

    // prologue: stage 0 direct to smem
    {
        float4 va0 = *(const float4*)(A + (size_t)(m0 + aRow0) * DIM + aK0);
        float4 va1 = *(const float4*)(A + (size_t)(m0 + aRow1) * DIM + aK1);
        uint32_t* d0 = &As[0][aRow0 * 20 + aK0];
        d0[0] = f2tf(va0.x); d0[1] = f2tf(va0.y); d0[2] = f2tf(va0.z); d0[3] = f2tf(va0.w);
        uint32_t* d1 = &As[0][aRow1 * 20 + aK1];
        d1[0] = f2tf(va1.x); d1[1] = f2tf(va1.y); d1[2] = f2tf(va1.z); d1[3] = f2tf(va1.w);
        float4 vb0 = make_float4(0.f, 0.f, 0.f, 0.f), vb1 = vb0;
        if (bOk0) vb0 = *(const float4*)(B + (size_t)bRow0 * NPIX + n0 + bC0);
        if (bOk1) vb1 = *(const float4*)(B + (size_t)bRow1 * NPIX + n0 + bC1);
        uint32_t* e0 = &Bs[0][bRow0 * 136 + bC0];
        e0[0] = f2tf(vb0.x); e0[1] = f2tf(vb0.y); e0[2] = f2tf(vb0.z); e0[3] = f2tf(vb0.w);
        uint32_t* e1 = &Bs[0][bRow1 * 136 + bC1];
        e1[0] = f2tf(vb1.x); e1[1] = f2tf(vb1.y); e1[2] = f2tf(vb1.z); e1[3] = f2tf(vb1.w);
    }
    __syncthreads();

    const int NS = DIM / 16;
    for (int s = 0; s < NS; s++) {
        float4 pa0, pa1, pb0, pb1;
        bool more = (s + 1) < NS;
        if (more) {
            int k0 = (s + 1) * 16;
            pa0 = *(const float4*)(A + (size_t)(m0 + aRow0) * DIM + k0 + aK0);
            pa1 = *(const float4*)(A + (size_t)(m0 + aRow1) * DIM + k0 + aK1);
            pb0 = pb1 = make_float4(0.f, 0.f, 0.f, 0.f);
            if (bOk0) pb0 = *(const float4*)(B + (size_t)(k0 + bRow0) * NPIX + n0 + bC0);
            if (bOk1) pb1 = *(const float4*)(B + (size_t)(k0 + bRow1) * NPIX + n0 + bC1);
        }

        int buf = s & 1;
        const uint32_t* Ab = As[buf];
        const uint32_t* Bb = Bs[buf];
#pragma unroll
        for (int ks = 0; ks < 2; ks++) {
            int k = ks * 8;
            uint32_t af[4][4], bf[4][2];
#pragma unroll
            for (int mt = 0; mt < 4; mt++) {
                int r = wm + mt * 16 + (lane >> 2);
                int cc = k + (lane & 3);
                af[mt][0] = Ab[r * 20 + cc];
                af[mt][1] = Ab[(r + 8) * 20 + cc];
                af[mt][2] = Ab[r * 20 + cc + 4];
                af[mt][3] = Ab[(r + 8) * 20 + cc + 4];
            }
#pragma unroll
            for (int nt = 0; nt < 4; nt++) {
                int nn = wn + nt * 8 + (lane >> 2);
                bf[nt][0] = Bb[(k + (lane & 3)) * 136 + nn];
                bf[nt][1] = Bb[(k + 4 + (lane & 3)) * 136 + nn];
            }
#pragma unroll
            for (int mt = 0; mt < 4; mt++)
#pragma unroll
                for (int nt = 0; nt < 4; nt++)
                    mma_tf32(acc[mt][nt], af[mt], bf[nt]);
        }

        if (more) {
            int nbuf = (s + 1) & 1;
            uint32_t* d0 = &As[nbuf][aRow0 * 20 + aK0];
            d0[0] = f2tf(pa0.x); d0[1] = f2tf(pa0.y); d0[2] = f2tf(pa0.z); d0[3] = f2tf(pa0.w);
            uint32_t* d1 = &As[nbuf][aRow1 * 20 + aK1];
            d1[0] = f2tf(pa1.x); d1[1] = f2tf(pa1.y); d1[2] = f2tf(pa1.z); d1[3] = f2tf(pa1.w);
            uint32_t* e0 = &Bs[nbuf][bRow0 * 136 + bC0];
            e0[0] = f2tf(pb0.x); e0[1] = f2tf(pb0.y); e0[2] = f2tf(pb0.z); e0[3] = f2tf(pb0.w);
            uint32_t* e1 = &Bs[nbuf][bRow1 * 136 + bC1];
            e1[0] = f2tf(pb1.x); e1[1] = f2tf(pb1.y); e1[2] = f2tf(pb1.z); e1[3] = f2tf(pb1.w);
        }
        __syncthreads();
    }

    float* Out = g_qkv[pr] + (size_t)b * INNER * NPIX;
#pragma unroll
    for (int mt = 0; mt < 4; mt++) {
#pragma unroll
        for (int rr = 0; rr < 2; rr++) {
            int m = m0 + wm + mt * 16 + (lane >> 2) + rr * 8;
#pragma unroll
            for (int nt = 0; nt < 4; nt++) {
                int n = n0 + wn + nt * 8 + (lane & 3) * 2;
                if (n < NPIX) {
                    float2 v;
                    v.x = acc[mt][nt][rr * 2 + 0];
                    v.y = acc[mt][nt][rr * 2 + 1];
                    *(float2*)&Out[(size_t)m * NPIX + n] = v;
                }
            }
        }
    }
}

// ---------------------------------------------------------------------------
// Kernel E (tf32 TC, double-buffered): out[co,pix] = out_w*att + bias
// ---------------------------------------------------------------------------
__global__ void __launch_bounds__(256, 2) out_gemm_tc(
    const float* __restrict__ A, const float* __restrict__ ob,
    float* __restrict__ out)
{
    __shared__ uint32_t As[2][128 * 20];
    __shared__ uint32_t Bs[2][16 * 136];

    int nb = blockIdx.x;                 // 0..24
    int mb = blockIdx.y;                 // 0..1
    int b  = blockIdx.z;                 // 0..15
    const float* B = g_att + (size_t)b * INNER * NPIX;

    int tid = threadIdx.x;
    int lane = tid & 31, warp = tid >> 5;
    int wm = (warp & 1) * 64;
    int wn = (warp >> 1) * 32;
    int m0 = mb * 128, n0 = nb * 128;

    int aRow0 = (tid * 2) >> 2,     aK0 = ((tid * 2) & 3) * 4;
    int aRow1 = (tid * 2 + 1) >> 2, aK1 = ((tid * 2 + 1) & 3) * 4;
    int bRow0 = (tid * 2) >> 5,     bC0 = ((tid * 2) & 31) * 4;
    int bRow1 = (tid * 2 + 1) >> 5, bC1 = ((tid * 2 + 1) & 31) * 4;
    bool bOk0 = (n0 + bC0) < NPIX, bOk1 = (n0 + bC1) < NPIX;

    float acc[4][4][4];
#pragma unroll
    for (int mt = 0; mt < 4; mt++)
#pragma unroll
        for (int nt = 0; nt < 4; nt++)
#pragma unroll
            for (int i = 0; i < 4; i++) acc[mt][nt][i] = 0.f;

    {
        float4 va0 = *(const float4*)(A + (size_t)(m0 + aRow0) * INNER + aK0);
        float4 va1 = *(const float4*)(A + (size_t)(m0 + aRow1) * INNER + aK1);
        uint32_t* d0 = &As[0][aRow0 * 20 + aK0];
        d0[0] = f2tf(va0.x); d0[1] = f2tf(va0.y); d0[2] = f2tf(va0.z); d0[3] = f2tf(va0.w);
        uint32_t* d1 = &As[0][aRow1 * 20 + aK1];
        d1[0] = f2tf(va1.x); d1[1] = f2tf(va1.y); d1[2] = f2tf(va1.z); d1[3] = f2tf(va1.w);
        float4 vb0 = make_float4(0.f, 0.f, 0.f, 0.f), vb1 = vb0;
        if (bOk0) vb0 = *(const float4*)(B + (size_t)bRow0 * NPIX + n0 + bC0);
        if (bOk1) vb1 = *(const float4*)(B + (size_t)bRow1 * NPIX + n0 + bC1);
        uint32_t* e0 = &Bs[0][bRow0 * 136 + bC0];
        e0[0] = f2tf(vb0.x); e0[1] = f2tf(vb0.y); e0[2] = f2tf(vb0.z); e0[3] = f2tf(vb0.w);
        uint32_t* e1 = &Bs[0][bRow1 * 136 + bC1];
        e1[0] = f2tf(vb1.x); e1[1] = f2tf(vb1.y); e1[2] = f2tf(vb1.z); e1[3] = f2tf(vb1.w);
    }
    __syncthreads();

    const int NS = INNER / 16;
    for (int s = 0; s < NS; s++) {
        float4 pa0, pa1, pb0, pb1;
        bool more = (s + 1) < NS;
        if (more) {
            int k0 = (s + 1) * 16;
            pa0 = *(const float4*)(A + (size_t)(m0 + aRow0) * INNER + k0 + aK0);
            pa1 = *(const float4*)(A + (size_t)(m0 + aRow1) * INNER + k0 + aK1);
            pb0 = pb1 = make_float4(0.f, 0.f, 0.f, 0.f);
            if (bOk0) pb0 = *(const float4*)(B + (size_t)(k0 + bRow0) * NPIX + n0 + bC0);
            if (bOk1) pb1 = *(const float4*)(B + (size_t)(k0 + bRow1) * NPIX + n0 + bC1);
        }

        int buf = s & 1;
        const uint32_t* Ab = As[buf];
        const uint32_t* Bb = Bs[buf];
#pragma unroll
        for (int ks = 0; ks < 2; ks++) {
            int k = ks * 8;
            uint32_t af[4][4], bf[4][2];
#pragma unroll
            for (int mt = 0; mt < 4; mt++) {
                int r = wm + mt * 16 + (lane >> 2);
                int cc = k + (lane & 3);
                af[mt][0] = Ab[r * 20 + cc];
                af[mt][1] = Ab[(r + 8) * 20 + cc];
                af[mt][2] = Ab[r * 20 + cc + 4];
                af[mt][3] = Ab[(r + 8) * 20 + cc + 4];
            }
#pragma unroll
            for (int nt = 0; nt < 4; nt++) {
                int nn = wn + nt * 8 + (lane >> 2);
                bf[nt][0] = Bb[(k + (lane & 3)) * 136 + nn];
                bf[nt][1] = Bb[(k + 4 + (lane & 3)) * 136 + nn];
            }
#pragma unroll
            for (int mt = 0; mt < 4; mt++)
#pragma unroll
                for (int nt = 0; nt < 4; nt++)
                    mma_tf32(acc[mt][nt], af[mt], bf[nt]);
        }

        if (more) {
            int nbuf = (s + 1) & 1;
            uint32_t* d0 = &As[nbuf][aRow0 * 20 + aK0];
            d0[0] = f2tf(pa0.x); d0[1] = f2tf(pa0.y); d0[2] = f2tf(pa0.z); d0[3] = f2tf(pa0.w);
            uint32_t* d1 = &As[nbuf][aRow1 * 20 + aK1];
            d1[0] = f2tf(pa1.x); d1[1] = f2tf(pa1.y); d1[2] = f2tf(pa1.z); d1[3] = f2tf(pa1.w);
            uint32_t* e0 = &Bs[nbuf][bRow0 * 136 + bC0];
            e0[0] = f2tf(pb0.x); e0[1] = f2tf(pb0.y); e0[2] = f2tf(pb0.z); e0[3] = f2tf(pb0.w);
            uint32_t* e1 = &Bs[nbuf][bRow1 * 136 + bC1];
            e1[0] = f2tf(pb1.x); e1[1] = f2tf(pb1.y); e1[2] = f2tf(pb1.z); e1[3] = f2tf(pb1.w);
        }
        __syncthreads();
    }

#pragma unroll
    for (int mt = 0; mt < 4; mt++) {
#pragma unroll
        for (int rr = 0; rr < 2; rr++) {
            int m = m0 + wm + mt * 16 + (lane >> 2) + rr * 8;
            float bias = __ldg(ob + m);
#pragma unroll
            for (int nt = 0; nt < 4; nt++) {
                int n = n0 + wn + nt * 8 + (lane & 3) * 2;
                if (n < NPIX) {
                    float2 v;
                    v.x = acc[mt][nt][rr * 2 + 0] + bias;
                    v.y = acc[mt][nt][rr * 2 + 1] + bias;
                    *(float2*)&out[(size_t)(b * DIM + m) * NPIX + n] = v;
                }
            }
        }
    }
}

// ---------------------------------------------------------------------------
// Kernel D (tf32 TC): windowed attention. One CTA per (b, h, w).
// One-pass quad-per-row softmax; ALL lanes run the shuffles (no divergent
// shfl with full mask — that deadlocked R4); only stores are guarded.
// ---------------------------------------------------------------------------
__global__ void __launch_bounds__(256) attn_tc() {
    __shared__ uint32_t qs[64 * 68];   // Q tf32 [t][d]; later attnS (float) [i][j]
    __shared__ uint32_t ks[56 * 68];   // K tf32 [t][d]
    __shared__ uint32_t vs[64 * 60];   // V tf32 [d][t]

    int w = blockIdx.x, h = blockIdx.y, b = blockIdx.z;
    int tid = threadIdx.x, lane = tid & 31, warp = tid >> 5;
    int nh = w >> 3, nw2 = w & 7;
    int px0 = (nh * 7) * 56 + nw2 * 7;

    size_t cbase = ((size_t)b * INNER + h * DHEAD) * NPIX;
    const float* qg = g_qkv[0] + cbase;
    const float* kg = g_qkv[1] + cbase;
    const float* vg = g_qkv[2] + cbase;

    for (int idx = tid; idx < DHEAD * NTOK; idx += 256) {
        int d = idx / NTOK, t = idx - d * NTOK;
        int poff = px0 + (t / 7) * 56 + (t % 7);
        size_t g = (size_t)d * NPIX + poff;
        qs[t * 68 + d] = f2tf(__ldg(qg + g));
        ks[t * 68 + d] = f2tf(__ldg(kg + g));
        vs[d * 60 + t] = f2tf(__ldg(vg + g));
    }
    for (int idx = tid; idx < DHEAD * 7; idx += 256) {
        int d = idx / 7, t = NTOK + idx % 7;
        vs[d * 60 + t] = 0u;
    }
    __syncthreads();

    int wm = (warp >> 1) * 16;          // m16 tile (i for QK, d for AV)
    int wn = (warp & 1) * 32;           // n half
    int ntmaxQK = (warp & 1) ? 3 : 4;   // N=56 for QK

    // ---- QK^T
    float acc[4][4];
#pragma unroll
    for (int nt = 0; nt < 4; nt++)
#pragma unroll
        for (int i = 0; i < 4; i++) acc[nt][i] = 0.f;

#pragma unroll
    for (int ks8 = 0; ks8 < 8; ks8++) {
        int k0 = ks8 * 8;
        int r = wm + (lane >> 2), kk = k0 + (lane & 3);
        uint32_t af[4];
        af[0] = qs[r * 68 + kk];
        af[1] = qs[(r + 8) * 68 + kk];
        af[2] = qs[r * 68 + kk + 4];
        af[3] = qs[(r + 8) * 68 + kk + 4];
#pragma unroll
        for (int nt = 0; nt < 4; nt++) {
            if (nt < ntmaxQK) {
                int n = wn + nt * 8 + (lane >> 2);
                uint32_t bf[2];
                bf[0] = ks[n * 68 + kk];
                bf[1] = ks[n * 68 + kk + 4];
                mma_tf32(acc[nt], af, bf);
            }
        }
    }
    __syncthreads();  // all warps done reading qs before aliasing

    // ---- write dots (+bias) into attnS (alias of qs)
    float* attnS = (float*)qs;
    const float* bptr = g_bias + h * NTOK * NTOK;
#pragma unroll
    for (int nt = 0; nt < 4; nt++) {
        if (nt < ntmaxQK) {
#pragma unroll
            for (int rr = 0; rr < 2; rr++) {
                int i = wm + (lane >> 2) + rr * 8;
                if (i < NTOK) {
#pragma unroll
                    for (int c = 0; c < 2; c++) {
                        int j = wn + nt * 8 + (lane & 3) * 2 + c;
                        if (j < NTOK)
                            attnS[i * 68 + j] = acc[nt][rr * 2 + c] * 0.125f
                                              + __ldg(bptr + i * NTOK + j);
                    }
                }
            }
        }
    }
    __syncthreads();

    // ---- softmax: one pass, quad (4 lanes) per row; all lanes participate.
    {
        int qd = lane >> 2, ql = lane & 3;
        int i = warp * 8 + qd;           // 0..63; rows >=49 compute garbage, never stored
        bool rowOk = (i < NTOK);
        float v[14];
        float mx = -1e30f;
#pragma unroll
        for (int it = 0; it < 14; it++) {
            int j = ql + it * 4;         // up to 55
            v[it] = (rowOk && j < NTOK) ? attnS[i * 68 + j] : -1e30f;
            mx = fmaxf(mx, v[it]);
        }
        mx = fmaxf(mx, __shfl_xor_sync(0xffffffffu, mx, 1));
        mx = fmaxf(mx, __shfl_xor_sync(0xffffffffu, mx, 2));
        float s = 0.f;
#pragma unroll
        for (int it = 0; it < 14; it++) {
            int j = ql + it * 4;
            float e = (rowOk && j < NTOK) ? __expf(v[it] - mx) : 0.f;
            v[it] = e;
            s += e;
        }
        s += __shfl_xor_sync(0xffffffffu, s, 1);
        s += __shfl_xor_sync(0xffffffffu, s, 2);
        float inv = 1.f / s;             // garbage for rowOk==false; unused
        if (rowOk) {
#pragma unroll
            for (int it = 0; it < 14; it++) {
                int j = ql + it * 4;
                attnS[i * 68 + j] = v[it] * inv;   // zeros for j=49..55 (K pad)
            }
        }
    }
    __syncthreads();

    // ---- AV: outT[d][i] = sum_j V[d][j] * attn[i][j]
    float acc2[4][4];
#pragma unroll
    for (int nt = 0; nt < 4; nt++)
#pragma unroll
        for (int i = 0; i < 4; i++) acc2[nt][i] = 0.f;

#pragma unroll
    for (int ks8 = 0; ks8 < 7; ks8++) {
        int k0 = ks8 * 8;
        int r = wm + (lane >> 2), kk = k0 + (lane & 3);
        uint32_t af[4];
        af[0] = vs[r * 60 + kk];
        af[1] = vs[(r + 8) * 60 + kk];
        af[2] = vs[r * 60 + kk + 4];
        af[3] = vs[(r + 8) * 60 + kk + 4];
#pragma unroll
        for (int nt = 0; nt < 4; nt++) {
            int n = wn + nt * 8 + (lane >> 2);
            uint32_t bf[2];
            bf[0] = (n < NTOK) ? f2tf(attnS[n * 68 + kk]) : 0u;
            bf[1] = (n < NTOK) ? f2tf(attnS[n * 68 + kk + 4]) : 0u;
            mma_tf32(acc2[nt], af, bf);
        }
    }

    // ---- store (un-window): plain [b][ci][y][x]
    float* outp = g_att + (size_t)b * INNER * NPIX + (size_t)h * DHEAD * NPIX;
#pragma unroll
    for (int nt = 0; nt < 4; nt++) {
#pragma unroll
        for (int c = 0; c < 2; c++) {
            int i = wn + nt * 8 + (lane & 3) * 2 + c;
            if (i < NTOK) {
                int poff = px0 + (i / 7) * 56 + (i % 7);
#pragma unroll
                for (int rr = 0; rr < 2; rr++) {
                    int d = wm + (lane >> 2) + rr * 8;
                    outp[(size_t)d * NPIX + poff] = acc2[nt][rr * 2 + c];
                }
            }
        }
    }
}

// ---------------------------------------------------------------------------
extern "C" void kernel_launch(void* const* d_in, const int* in_sizes, int n_in,
                              void* d_out, int out_size) {
    const float* x   = (const float*)d_in[0];
    const float* qdw = (const float*)d_in[1];
    const float* qg  = (const float*)d_in[2];
    const float* qb  = (const float*)d_in[3];
    const float* qm  = (const float*)d_in[4];
    const float* qv  = (const float*)d_in[5];
    const float* qpw = (const float*)d_in[6];
    const float* kdw = (const float*)d_in[7];
    const float* kg  = (const float*)d_in[8];
    const float* kb  = (const float*)d_in[9];
    const float* km  = (const float*)d_in[10];
    const float* kv  = (const float*)d_in[11];
    const float* kpw = (const float*)d_in[12];
    const float* vdw = (const float*)d_in[13];
    const float* vg  = (const float*)d_in[14];
    const float* vb  = (const float*)d_in[15];
    const float* vm  = (const float*)d_in[16];
    const float* vv  = (const float*)d_in[17];
    const float* vpw = (const float*)d_in[18];
    const float* pos = (const float*)d_in[19];
    const float* ow  = (const float*)d_in[20];
    const float* obias = (const float*)d_in[21];
    float* out = (float*)d_out;

    bias_kernel<<<(HEADS * NTOK * NTOK + 255) / 256, 256>>>(pos);

    dwbn_kernel<<<dim3((NPIX + 255) / 256, BATCH * DIM), 256>>>(
        x, qdw, qg, qb, qm, qv, kdw, kg, kb, km, kv, vdw, vg, vb, vm, vv);

    proj_gemm_tc<<<dim3(25, 4, BATCH * 3), 256>>>(qpw, kpw, vpw);

    attn_tc<<<dim3(NWIN, HEADS, BATCH), 256>>>();

    out_gemm_tc<<<dim3(25, 2, BATCH), 256>>>(ow, obias, out);
}

// round 6
// speedup vs baseline: 2.2679x; 1.0698x over previous
#include <cuda_runtime.h>
#include <math.h>
#include <stdint.h>

#define DIM    256
#define INNER  512
#define HEADS  8
#define DHEAD  64
#define NTOK   49
#define NPIX   3136
#define BATCH  16
#define NWIN   64
#define EPS    1e-5f

// Scratch (allocation-free: __device__ globals)
__device__ float g_y[3][BATCH * DIM * NPIX];      // dwconv+BN outputs (q,k,v): [b][c][pix]
__device__ float g_qkv[3][BATCH * INNER * NPIX];  // projected, PLAIN layout: [b][c][pix]
__device__ float g_att[BATCH * INNER * NPIX];     // attention out, plain: [b][ci][y][x]
__device__ float g_bias[HEADS * NTOK * NTOK];     // rel-pos bias: [h][i][j]

// ---------------------------------------------------------------------------
// tf32 helpers
// ---------------------------------------------------------------------------
__device__ __forceinline__ uint32_t f2tf(float f) {
    uint32_t u;
    asm("cvt.rna.tf32.f32 %0, %1;" : "=r"(u) : "f"(f));
    return u;
}

__device__ __forceinline__ void mma_tf32(float c[4], const uint32_t a[4], const uint32_t b[2]) {
    asm volatile(
        "mma.sync.aligned.m16n8k8.row.col.f32.tf32.tf32.f32 "
        "{%0,%1,%2,%3}, {%4,%5,%6,%7}, {%8,%9}, {%0,%1,%2,%3};\n"
        : "+f"(c[0]), "+f"(c[1]), "+f"(c[2]), "+f"(c[3])
        : "r"(a[0]), "r"(a[1]), "r"(a[2]), "r"(a[3]), "r"(b[0]), "r"(b[1]));
}

// ---------------------------------------------------------------------------
// Kernel C: precompute relative position bias table [h][i][j]
// ---------------------------------------------------------------------------
__global__ void bias_kernel(const float* __restrict__ pos) {
    int idx = blockIdx.x * 256 + threadIdx.x;
    if (idx >= HEADS * NTOK * NTOK) return;
    int h = idx / (NTOK * NTOK);
    int r = idx % (NTOK * NTOK);
    int i = r / NTOK, j = r % NTOK;
    int xi = i / 7, yi = i % 7, xj = j / 7, yj = j % 7;
    int rel = (xj - xi + 6) * 13 + (yj - yi + 6);
    g_bias[idx] = __ldg(pos + rel * HEADS + h);
}

// ---------------------------------------------------------------------------
// Kernel A: depthwise 3x3 conv + BN, 4 row-aligned pixels per thread,
// tap reuse across neighbors, float4 stores, all 3 projections per thread.
// ---------------------------------------------------------------------------
__global__ void __launch_bounds__(256) dwbn_kernel(
    const float* __restrict__ x,
    const float* __restrict__ dwq, const float* __restrict__ gq, const float* __restrict__ bq,
    const float* __restrict__ mq,  const float* __restrict__ vq,
    const float* __restrict__ dwk, const float* __restrict__ gk, const float* __restrict__ bk,
    const float* __restrict__ mk,  const float* __restrict__ vk,
    const float* __restrict__ dwv, const float* __restrict__ gv, const float* __restrict__ bv,
    const float* __restrict__ mv,  const float* __restrict__ vv)
{
    int pg = blockIdx.x * 256 + threadIdx.x;       // pixel-group (4 pixels)
    if (pg >= NPIX / 4) return;
    int p0 = pg * 4;
    int bc = blockIdx.y;            // b*256 + c
    int c  = bc & (DIM - 1);
    const float* xp = x + (size_t)bc * NPIX;
    int y0 = p0 / 56, x0 = p0 % 56;                // x0 in {0,4,...,52}; never crosses row

    // taps: rows y0-1..y0+1, cols x0-1..x0+4 (6 wide)
    float t[3][6];
#pragma unroll
    for (int dy = 0; dy < 3; dy++) {
        int yy = y0 + dy - 1;
        bool rowOk = (yy >= 0 && yy < 56);
        const float* rp = xp + yy * 56;
        t[dy][0] = (rowOk && x0 > 0) ? __ldg(rp + x0 - 1) : 0.f;
        if (rowOk) {
            float4 mid = *(const float4*)(rp + x0);   // x0 mult of 4 -> aligned
            t[dy][1] = mid.x; t[dy][2] = mid.y; t[dy][3] = mid.z; t[dy][4] = mid.w;
        } else {
            t[dy][1] = t[dy][2] = t[dy][3] = t[dy][4] = 0.f;
        }
        t[dy][5] = (rowOk && x0 + 4 < 56) ? __ldg(rp + x0 + 4) : 0.f;
    }

    const float* DW[3] = {dwq, dwk, dwv};
    const float* GG[3] = {gq, gk, gv};
    const float* BB[3] = {bq, bk, bv};
    const float* MM[3] = {mq, mk, mv};
    const float* VV[3] = {vq, vk, vv};

#pragma unroll
    for (int pr = 0; pr < 3; pr++) {
        const float* wp = DW[pr] + c * 9;
        float w[9];
#pragma unroll
        for (int j = 0; j < 9; j++) w[j] = __ldg(wp + j);

        float o[4] = {0.f, 0.f, 0.f, 0.f};
#pragma unroll
        for (int dy = 0; dy < 3; dy++)
#pragma unroll
            for (int dx = 0; dx < 3; dx++) {
                float ww = w[dy * 3 + dx];
#pragma unroll
                for (int i = 0; i < 4; i++)
                    o[i] += ww * t[dy][i + dx];
            }

        float sc = __ldg(GG[pr] + c) * rsqrtf(__ldg(VV[pr] + c) + EPS);
        float sh = __ldg(BB[pr] + c) - __ldg(MM[pr] + c) * sc;
        float4 res;
        res.x = o[0] * sc + sh;
        res.y = o[1] * sc + sh;
        res.z = o[2] * sc + sh;
        res.w = o[3] * sc + sh;
        *(float4*)&g_y[pr][(size_t)bc * NPIX + p0] = res;
    }
}

// ---------------------------------------------------------------------------
// Kernel B (tf32 TC, double-buffered): proj GEMM out[inner,pix]=pw*y
// BM=128, BN=128, BK=16; 8 warps (2x4), warp tile 64x32.
// blockIdx.x = mb (fastest) so CTAs sharing the B tile run in the same wave.
// ---------------------------------------------------------------------------
__global__ void __launch_bounds__(256, 2) proj_gemm_tc(
    const float* __restrict__ pw0, const float* __restrict__ pw1,
    const float* __restrict__ pw2)
{
    __shared__ uint32_t As[2][128 * 20];
    __shared__ uint32_t Bs[2][16 * 136];

    int mb = blockIdx.x;                 // 0..3  (fastest -> L2 B-tile reuse)
    int nb = blockIdx.y;                 // 0..24
    int bz = blockIdx.z;                 // b*3 + proj
    int pr = bz % 3, b = bz / 3;
    const float* A = (pr == 0) ? pw0 : ((pr == 1) ? pw1 : pw2);
    const float* B = g_y[pr] + (size_t)b * DIM * NPIX;

    int tid = threadIdx.x;
    int lane = tid & 31, warp = tid >> 5;
    int wm = (warp & 1) * 64;
    int wn = (warp >> 1) * 32;
    int m0 = mb * 128, n0 = nb * 128;

    // per-thread load coords (fixed across stages)
    int aRow0 = (tid * 2) >> 2,     aK0 = ((tid * 2) & 3) * 4;
    int aRow1 = (tid * 2 + 1) >> 2, aK1 = ((tid * 2 + 1) & 3) * 4;
    int bRow0 = (tid * 2) >> 5,     bC0 = ((tid * 2) & 31) * 4;
    int bRow1 = (tid * 2 + 1) >> 5, bC1 = ((tid * 2 + 1) & 31) * 4;
    bool bOk0 = (n0 + bC0) < NPIX, bOk1 = (n0 + bC1) < NPIX;

    float acc[4][4][4];
#pragma unroll
    for (int mt = 0; mt < 4; mt++)
#pragma unroll
        for (int nt = 0; nt < 4; nt++)
#pragma unroll
            for (int i = 0; i < 4; i++) acc[mt][nt][i] = 0.f;

    // prologue: stage 0 direct to smem
    {
        float4 va0 = *(const float4*)(A + (size_t)(m0 + aRow0) * DIM + aK0);
        float4 va1 = *(const float4*)(A + (size_t)(m0 + aRow1) * DIM + aK1);
        uint32_t* d0 = &As[0][aRow0 * 20 + aK0];
        d0[0] = f2tf(va0.x); d0[1] = f2tf(va0.y); d0[2] = f2tf(va0.z); d0[3] = f2tf(va0.w);
        uint32_t* d1 = &As[0][aRow1 * 20 + aK1];
        d1[0] = f2tf(va1.x); d1[1] = f2tf(va1.y); d1[2] = f2tf(va1.z); d1[3] = f2tf(va1.w);
        float4 vb0 = make_float4(0.f, 0.f, 0.f, 0.f), vb1 = vb0;
        if (bOk0) vb0 = *(const float4*)(B + (size_t)bRow0 * NPIX + n0 + bC0);
        if (bOk1) vb1 = *(const float4*)(B + (size_t)bRow1 * NPIX + n0 + bC1);
        uint32_t* e0 = &Bs[0][bRow0 * 136 + bC0];
        e0[0] = f2tf(vb0.x); e0[1] = f2tf(vb0.y); e0[2] = f2tf(vb0.z); e0[3] = f2tf(vb0.w);
        uint32_t* e1 = &Bs[0][bRow1 * 136 + bC1];
        e1[0] = f2tf(vb1.x); e1[1] = f2tf(vb1.y); e1[2] = f2tf(vb1.z); e1[3] = f2tf(vb1.w);
    }
    __syncthreads();

    const int NS = DIM / 16;
    for (int s = 0; s < NS; s++) {
        float4 pa0, pa1, pb0, pb1;
        bool more = (s + 1) < NS;
        if (more) {
            int k0 = (s + 1) * 16;
            pa0 = *(const float4*)(A + (size_t)(m0 + aRow0) * DIM + k0 + aK0);
            pa1 = *(const float4*)(A + (size_t)(m0 + aRow1) * DIM + k0 + aK1);
            pb0 = pb1 = make_float4(0.f, 0.f, 0.f, 0.f);
            if (bOk0) pb0 = *(const float4*)(B + (size_t)(k0 + bRow0) * NPIX + n0 + bC0);
            if (bOk1) pb1 = *(const float4*)(B + (size_t)(k0 + bRow1) * NPIX + n0 + bC1);
        }

        int buf = s & 1;
        const uint32_t* Ab = As[buf];
        const uint32_t* Bb = Bs[buf];
#pragma unroll
        for (int ks = 0; ks < 2; ks++) {
            int k = ks * 8;
            uint32_t af[4][4], bf[4][2];
#pragma unroll
            for (int mt = 0; mt < 4; mt++) {
                int r = wm + mt * 16 + (lane >> 2);
                int cc = k + (lane & 3);
                af[mt][0] = Ab[r * 20 + cc];
                af[mt][1] = Ab[(r + 8) * 20 + cc];
                af[mt][2] = Ab[r * 20 + cc + 4];
                af[mt][3] = Ab[(r + 8) * 20 + cc + 4];
            }
#pragma unroll
            for (int nt = 0; nt < 4; nt++) {
                int nn = wn + nt * 8 + (lane >> 2);
                bf[nt][0] = Bb[(k + (lane & 3)) * 136 + nn];
                bf[nt][1] = Bb[(k + 4 + (lane & 3)) * 136 + nn];
            }
#pragma unroll
            for (int mt = 0; mt < 4; mt++)
#pragma unroll
                for (int nt = 0; nt < 4; nt++)
                    mma_tf32(acc[mt][nt], af[mt], bf[nt]);
        }

        if (more) {
            int nbuf = (s + 1) & 1;
            uint32_t* d0 = &As[nbuf][aRow0 * 20 + aK0];
            d0[0] = f2tf(pa0.x); d0[1] = f2tf(pa0.y); d0[2] = f2tf(pa0.z); d0[3] = f2tf(pa0.w);
            uint32_t* d1 = &As[nbuf][aRow1 * 20 + aK1];
            d1[0] = f2tf(pa1.x); d1[1] = f2tf(pa1.y); d1[2] = f2tf(pa1.z); d1[3] = f2tf(pa1.w);
            uint32_t* e0 = &Bs[nbuf][bRow0 * 136 + bC0];
            e0[0] = f2tf(pb0.x); e0[1] = f2tf(pb0.y); e0[2] = f2tf(pb0.z); e0[3] = f2tf(pb0.w);
            uint32_t* e1 = &Bs[nbuf][bRow1 * 136 + bC1];
            e1[0] = f2tf(pb1.x); e1[1] = f2tf(pb1.y); e1[2] = f2tf(pb1.z); e1[3] = f2tf(pb1.w);
        }
        __syncthreads();
    }

    float* Out = g_qkv[pr] + (size_t)b * INNER * NPIX;
#pragma unroll
    for (int mt = 0; mt < 4; mt++) {
#pragma unroll
        for (int rr = 0; rr < 2; rr++) {
            int m = m0 + wm + mt * 16 + (lane >> 2) + rr * 8;
#pragma unroll
            for (int nt = 0; nt < 4; nt++) {
                int n = n0 + wn + nt * 8 + (lane & 3) * 2;
                if (n < NPIX) {
                    float2 v;
                    v.x = acc[mt][nt][rr * 2 + 0];
                    v.y = acc[mt][nt][rr * 2 + 1];
                    *(float2*)&Out[(size_t)m * NPIX + n] = v;
                }
            }
        }
    }
}

// ---------------------------------------------------------------------------
// Kernel E (tf32 TC, double-buffered): out[co,pix] = out_w*att + bias
// blockIdx.x = mb (fastest) for L2 B-tile reuse.
// ---------------------------------------------------------------------------
__global__ void __launch_bounds__(256, 2) out_gemm_tc(
    const float* __restrict__ A, const float* __restrict__ ob,
    float* __restrict__ out)
{
    __shared__ uint32_t As[2][128 * 20];
    __shared__ uint32_t Bs[2][16 * 136];

    int mb = blockIdx.x;                 // 0..1 (fastest)
    int nb = blockIdx.y;                 // 0..24
    int b  = blockIdx.z;                 // 0..15
    const float* B = g_att + (size_t)b * INNER * NPIX;

    int tid = threadIdx.x;
    int lane = tid & 31, warp = tid >> 5;
    int wm = (warp & 1) * 64;
    int wn = (warp >> 1) * 32;
    int m0 = mb * 128, n0 = nb * 128;

    int aRow0 = (tid * 2) >> 2,     aK0 = ((tid * 2) & 3) * 4;
    int aRow1 = (tid * 2 + 1) >> 2, aK1 = ((tid * 2 + 1) & 3) * 4;
    int bRow0 = (tid * 2) >> 5,     bC0 = ((tid * 2) & 31) * 4;
    int bRow1 = (tid * 2 + 1) >> 5, bC1 = ((tid * 2 + 1) & 31) * 4;
    bool bOk0 = (n0 + bC0) < NPIX, bOk1 = (n0 + bC1) < NPIX;

    float acc[4][4][4];
#pragma unroll
    for (int mt = 0; mt < 4; mt++)
#pragma unroll
        for (int nt = 0; nt < 4; nt++)
#pragma unroll
            for (int i = 0; i < 4; i++) acc[mt][nt][i] = 0.f;

    {
        float4 va0 = *(const float4*)(A + (size_t)(m0 + aRow0) * INNER + aK0);
        float4 va1 = *(const float4*)(A + (size_t)(m0 + aRow1) * INNER + aK1);
        uint32_t* d0 = &As[0][aRow0 * 20 + aK0];
        d0[0] = f2tf(va0.x); d0[1] = f2tf(va0.y); d0[2] = f2tf(va0.z); d0[3] = f2tf(va0.w);
        uint32_t* d1 = &As[0][aRow1 * 20 + aK1];
        d1[0] = f2tf(va1.x); d1[1] = f2tf(va1.y); d1[2] = f2tf(va1.z); d1[3] = f2tf(va1.w);
        float4 vb0 = make_float4(0.f, 0.f, 0.f, 0.f), vb1 = vb0;
        if (bOk0) vb0 = *(const float4*)(B + (size_t)bRow0 * NPIX + n0 + bC0);
        if (bOk1) vb1 = *(const float4*)(B + (size_t)bRow1 * NPIX + n0 + bC1);
        uint32_t* e0 = &Bs[0][bRow0 * 136 + bC0];
        e0[0] = f2tf(vb0.x); e0[1] = f2tf(vb0.y); e0[2] = f2tf(vb0.z); e0[3] = f2tf(vb0.w);
        uint32_t* e1 = &Bs[0][bRow1 * 136 + bC1];
        e1[0] = f2tf(vb1.x); e1[1] = f2tf(vb1.y); e1[2] = f2tf(vb1.z); e1[3] = f2tf(vb1.w);
    }
    __syncthreads();

    const int NS = INNER / 16;
    for (int s = 0; s < NS; s++) {
        float4 pa0, pa1, pb0, pb1;
        bool more = (s + 1) < NS;
        if (more) {
            int k0 = (s + 1) * 16;
            pa0 = *(const float4*)(A + (size_t)(m0 + aRow0) * INNER + k0 + aK0);
            pa1 = *(const float4*)(A + (size_t)(m0 + aRow1) * INNER + k0 + aK1);
            pb0 = pb1 = make_float4(0.f, 0.f, 0.f, 0.f);
            if (bOk0) pb0 = *(const float4*)(B + (size_t)(k0 + bRow0) * NPIX + n0 + bC0);
            if (bOk1) pb1 = *(const float4*)(B + (size_t)(k0 + bRow1) * NPIX + n0 + bC1);
        }

        int buf = s & 1;
        const uint32_t* Ab = As[buf];
        const uint32_t* Bb = Bs[buf];
#pragma unroll
        for (int ks = 0; ks < 2; ks++) {
            int k = ks * 8;
            uint32_t af[4][4], bf[4][2];
#pragma unroll
            for (int mt = 0; mt < 4; mt++) {
                int r = wm + mt * 16 + (lane >> 2);
                int cc = k + (lane & 3);
                af[mt][0] = Ab[r * 20 + cc];
                af[mt][1] = Ab[(r + 8) * 20 + cc];
                af[mt][2] = Ab[r * 20 + cc + 4];
                af[mt][3] = Ab[(r + 8) * 20 + cc + 4];
            }
#pragma unroll
            for (int nt = 0; nt < 4; nt++) {
                int nn = wn + nt * 8 + (lane >> 2);
                bf[nt][0] = Bb[(k + (lane & 3)) * 136 + nn];
                bf[nt][1] = Bb[(k + 4 + (lane & 3)) * 136 + nn];
            }
#pragma unroll
            for (int mt = 0; mt < 4; mt++)
#pragma unroll
                for (int nt = 0; nt < 4; nt++)
                    mma_tf32(acc[mt][nt], af[mt], bf[nt]);
        }

        if (more) {
            int nbuf = (s + 1) & 1;
            uint32_t* d0 = &As[nbuf][aRow0 * 20 + aK0];
            d0[0] = f2tf(pa0.x); d0[1] = f2tf(pa0.y); d0[2] = f2tf(pa0.z); d0[3] = f2tf(pa0.w);
            uint32_t* d1 = &As[nbuf][aRow1 * 20 + aK1];
            d1[0] = f2tf(pa1.x); d1[1] = f2tf(pa1.y); d1[2] = f2tf(pa1.z); d1[3] = f2tf(pa1.w);
            uint32_t* e0 = &Bs[nbuf][bRow0 * 136 + bC0];
            e0[0] = f2tf(pb0.x); e0[1] = f2tf(pb0.y); e0[2] = f2tf(pb0.z); e0[3] = f2tf(pb0.w);
            uint32_t* e1 = &Bs[nbuf][bRow1 * 136 + bC1];
            e1[0] = f2tf(pb1.x); e1[1] = f2tf(pb1.y); e1[2] = f2tf(pb1.z); e1[3] = f2tf(pb1.w);
        }
        __syncthreads();
    }

#pragma unroll
    for (int mt = 0; mt < 4; mt++) {
#pragma unroll
        for (int rr = 0; rr < 2; rr++) {
            int m = m0 + wm + mt * 16 + (lane >> 2) + rr * 8;
            float bias = __ldg(ob + m);
#pragma unroll
            for (int nt = 0; nt < 4; nt++) {
                int n = n0 + wn + nt * 8 + (lane & 3) * 2;
                if (n < NPIX) {
                    float2 v;
                    v.x = acc[mt][nt][rr * 2 + 0] + bias;
                    v.y = acc[mt][nt][rr * 2 + 1] + bias;
                    *(float2*)&out[(size_t)(b * DIM + m) * NPIX + n] = v;
                }
            }
        }
    }
}

// ---------------------------------------------------------------------------
// Kernel D (tf32 TC): windowed attention. One CTA per (b, h, w).
// One-pass quad-per-row softmax; AV feeds raw fp32 bits (tf32 truncation).
// ---------------------------------------------------------------------------
__global__ void __launch_bounds__(256) attn_tc() {
    __shared__ uint32_t qs[64 * 68];   // Q tf32 [t][d]; later attnS (float) [i][j]
    __shared__ uint32_t ks[56 * 68];   // K tf32 [t][d]
    __shared__ uint32_t vs[64 * 60];   // V tf32 [d][t]

    int w = blockIdx.x, h = blockIdx.y, b = blockIdx.z;
    int tid = threadIdx.x, lane = tid & 31, warp = tid >> 5;
    int nh = w >> 3, nw2 = w & 7;
    int px0 = (nh * 7) * 56 + nw2 * 7;

    size_t cbase = ((size_t)b * INNER + h * DHEAD) * NPIX;
    const float* qg = g_qkv[0] + cbase;
    const float* kg = g_qkv[1] + cbase;
    const float* vg = g_qkv[2] + cbase;

    for (int idx = tid; idx < DHEAD * NTOK; idx += 256) {
        int d = idx / NTOK, t = idx - d * NTOK;
        int poff = px0 + (t / 7) * 56 + (t % 7);
        size_t g = (size_t)d * NPIX + poff;
        qs[t * 68 + d] = f2tf(__ldg(qg + g));
        ks[t * 68 + d] = f2tf(__ldg(kg + g));
        vs[d * 60 + t] = f2tf(__ldg(vg + g));
    }
    for (int idx = tid; idx < DHEAD * 7; idx += 256) {
        int d = idx / 7, t = NTOK + idx % 7;
        vs[d * 60 + t] = 0u;
    }
    __syncthreads();

    int wm = (warp >> 1) * 16;          // m16 tile (i for QK, d for AV)
    int wn = (warp & 1) * 32;           // n half
    int ntmaxQK = (warp & 1) ? 3 : 4;   // N=56 for QK

    // ---- QK^T
    float acc[4][4];
#pragma unroll
    for (int nt = 0; nt < 4; nt++)
#pragma unroll
        for (int i = 0; i < 4; i++) acc[nt][i] = 0.f;

#pragma unroll
    for (int ks8 = 0; ks8 < 8; ks8++) {
        int k0 = ks8 * 8;
        int r = wm + (lane >> 2), kk = k0 + (lane & 3);
        uint32_t af[4];
        af[0] = qs[r * 68 + kk];
        af[1] = qs[(r + 8) * 68 + kk];
        af[2] = qs[r * 68 + kk + 4];
        af[3] = qs[(r + 8) * 68 + kk + 4];
#pragma unroll
        for (int nt = 0; nt < 4; nt++) {
            if (nt < ntmaxQK) {
                int n = wn + nt * 8 + (lane >> 2);
                uint32_t bf[2];
                bf[0] = ks[n * 68 + kk];
                bf[1] = ks[n * 68 + kk + 4];
                mma_tf32(acc[nt], af, bf);
            }
        }
    }
    __syncthreads();  // all warps done reading qs before aliasing

    // ---- write dots (+bias) into attnS (alias of qs)
    float* attnS = (float*)qs;
    const float* bptr = g_bias + h * NTOK * NTOK;
#pragma unroll
    for (int nt = 0; nt < 4; nt++) {
        if (nt < ntmaxQK) {
#pragma unroll
            for (int rr = 0; rr < 2; rr++) {
                int i = wm + (lane >> 2) + rr * 8;
                if (i < NTOK) {
#pragma unroll
                    for (int c = 0; c < 2; c++) {
                        int j = wn + nt * 8 + (lane & 3) * 2 + c;
                        if (j < NTOK)
                            attnS[i * 68 + j] = acc[nt][rr * 2 + c] * 0.125f
                                              + __ldg(bptr + i * NTOK + j);
                    }
                }
            }
        }
    }
    __syncthreads();

    // ---- softmax: one pass, quad (4 lanes) per row; all lanes participate.
    {
        int qd = lane >> 2, ql = lane & 3;
        int i = warp * 8 + qd;           // 0..63; rows >=49 compute garbage, never stored
        bool rowOk = (i < NTOK);
        float v[14];
        float mx = -1e30f;
#pragma unroll
        for (int it = 0; it < 14; it++) {
            int j = ql + it * 4;         // up to 55
            v[it] = (rowOk && j < NTOK) ? attnS[i * 68 + j] : -1e30f;
            mx = fmaxf(mx, v[it]);
        }
        mx = fmaxf(mx, __shfl_xor_sync(0xffffffffu, mx, 1));
        mx = fmaxf(mx, __shfl_xor_sync(0xffffffffu, mx, 2));
        float s = 0.f;
#pragma unroll
        for (int it = 0; it < 14; it++) {
            int j = ql + it * 4;
            float e = (rowOk && j < NTOK) ? __expf(v[it] - mx) : 0.f;
            v[it] = e;
            s += e;
        }
        s += __shfl_xor_sync(0xffffffffu, s, 1);
        s += __shfl_xor_sync(0xffffffffu, s, 2);
        float inv = 1.f / s;             // garbage for rowOk==false; unused
        if (rowOk) {
#pragma unroll
            for (int it = 0; it < 14; it++) {
                int j = ql + it * 4;
                attnS[i * 68 + j] = v[it] * inv;   // zeros for j=49..55 (K pad)
            }
        }
    }
    __syncthreads();

    // ---- AV: outT[d][i] = sum_j V[d][j] * attn[i][j]; raw bits -> tf32 (RZ)
    const uint32_t* attnU = (const uint32_t*)attnS;
    float acc2[4][4];
#pragma unroll
    for (int nt = 0; nt < 4; nt++)
#pragma unroll
        for (int i = 0; i < 4; i++) acc2[nt][i] = 0.f;

#pragma unroll
    for (int ks8 = 0; ks8 < 7; ks8++) {
        int k0 = ks8 * 8;
        int r = wm + (lane >> 2), kk = k0 + (lane & 3);
        uint32_t af[4];
        af[0] = vs[r * 60 + kk];
        af[1] = vs[(r + 8) * 60 + kk];
        af[2] = vs[r * 60 + kk + 4];
        af[3] = vs[(r + 8) * 60 + kk + 4];
#pragma unroll
        for (int nt = 0; nt < 4; nt++) {
            int n = wn + nt * 8 + (lane >> 2);
            uint32_t bf[2];
            bf[0] = (n < NTOK) ? attnU[n * 68 + kk] : 0u;
            bf[1] = (n < NTOK) ? attnU[n * 68 + kk + 4] : 0u;
            mma_tf32(acc2[nt], af, bf);
        }
    }

    // ---- store (un-window): plain [b][ci][y][x]
    float* outp = g_att + (size_t)b * INNER * NPIX + (size_t)h * DHEAD * NPIX;
#pragma unroll
    for (int nt = 0; nt < 4; nt++) {
#pragma unroll
        for (int c = 0; c < 2; c++) {
            int i = wn + nt * 8 + (lane & 3) * 2 + c;
            if (i < NTOK) {
                int poff = px0 + (i / 7) * 56 + (i % 7);
#pragma unroll
                for (int rr = 0; rr < 2; rr++) {
                    int d = wm + (lane >> 2) + rr * 8;
                    outp[(size_t)d * NPIX + poff] = acc2[nt][rr * 2 + c];
                }
            }
        }
    }
}

// ---------------------------------------------------------------------------
extern "C" void kernel_launch(void* const* d_in, const int* in_sizes, int n_in,
                              void* d_out, int out_size) {
    const float* x   = (const float*)d_in[0];
    const float* qdw = (const float*)d_in[1];
    const float* qg  = (const float*)d_in[2];
    const float* qb  = (const float*)d_in[3];
    const float* qm  = (const float*)d_in[4];
    const float* qv  = (const float*)d_in[5];
    const float* qpw = (const float*)d_in[6];
    const float* kdw = (const float*)d_in[7];
    const float* kg  = (const float*)d_in[8];
    const float* kb  = (const float*)d_in[9];
    const float* km  = (const float*)d_in[10];
    const float* kv  = (const float*)d_in[11];
    const float* kpw = (const float*)d_in[12];
    const float* vdw = (const float*)d_in[13];
    const float* vg  = (const float*)d_in[14];
    const float* vb  = (const float*)d_in[15];
    const float* vm  = (const float*)d_in[16];
    const float* vv  = (const float*)d_in[17];
    const float* vpw = (const float*)d_in[18];
    const float* pos = (const float*)d_in[19];
    const float* ow  = (const float*)d_in[20];
    const float* obias = (const float*)d_in[21];
    float* out = (float*)d_out;

    bias_kernel<<<(HEADS * NTOK * NTOK + 255) / 256, 256>>>(pos);

    dwbn_kernel<<<dim3((NPIX / 4 + 255) / 256, BATCH * DIM), 256>>>(
        x, qdw, qg, qb, qm, qv, kdw, kg, kb, km, kv, vdw, vg, vb, vm, vv);

    proj_gemm_tc<<<dim3(4, 25, BATCH * 3), 256>>>(qpw, kpw, vpw);

    attn_tc<<<dim3(NWIN, HEADS, BATCH), 256>>>();

    out_gemm_tc<<<dim3(2, 25, BATCH), 256>>>(ow, obias, out);
}